// round 11
// baseline (speedup 1.0000x reference)
#include <cuda_runtime.h>

// Problem constants
#define BB 8
#define CC 32
#define DD 32
#define TT 32
#define HH 96
#define WW 96
#define MT 8
#define MS 16
#define BC (BB*CC)        // 256
#define BD (BB*DD)        // 256
#define HW (HH*WW)        // 9216
#define NMODE (MT*MS*MS)  // 2048
#define NROW (BC*MT*MS)   // 32768 rows of F2
#define TWO_PI 6.28318530717958647692f

// Y/Z smem row stride (floats). 144: h-parity offsets banks by 16 -> phase1/2
// LDS/STS conflict-free. smem = 2*96*144*4 = 110592 B -> 2 CTAs/SM.
#define ZSTR 144
#define SMEM_BYTES (2*HH*ZSTR*4)
// a1 transpose buffer stride (floats): [kx][136] -> reader banks fully spread
#define A1STR 136

// ---------------- scratch (static device globals; no allocation) ----------------
__device__ float g_F2r[WW*NROW];         // after T+H DFT, W-MAJOR: (w, bc*128+kt*16+kx)
__device__ float g_F2i[WW*NROW];
__device__ float g_F3r[BC*NMODE];        // after W-DFT: (bc, m)  m = kt*256+kx*16+ky
__device__ float g_F3i[BC*NMODE];
__device__ float g_Sr [BD*NMODE];        // after mix:   (bd, m)
__device__ float g_Si [BD*NMODE];

// ---------------- compile-time trig (Taylor, double precision) ----------------
__host__ __device__ constexpr double ct_cos(double x) {
    double x2 = x * x, t = 1.0, s = 1.0;
    for (int k = 1; k <= 26; k++) { t *= -x2 / ((2.0*k - 1.0) * (2.0*k)); s += t; }
    return s;
}
__host__ __device__ constexpr double ct_sin(double x) {
    double x2 = x * x, t = x, s = x;
    for (int k = 1; k <= 26; k++) { t *= -x2 / ((2.0*k) * (2.0*k + 1.0)); s += t; }
    return s;
}

// Twiddle cos/sin(2*pi*P/N) with exact 0 / +-1 at quadrant points
template<int P, int N> struct TW {
    static constexpr int    q0 = ((P % N) + N) % N;
    static constexpr int    aq = (q0 > N - q0) ? (N - q0) : q0;
    static constexpr int    ss = (q0 > N/2) ? -1 : 1;
    static constexpr bool c_zero = (4*aq == N);
    static constexpr bool s_zero = (aq == 0) || (2*aq == N);
    static constexpr float c =
        (aq == 0)     ? 1.0f  :
        (2*aq == N)   ? -1.0f :
        c_zero        ? 0.0f  :
        (float)ct_cos(6.283185307179586476925286766559 * (double)aq / (double)N);
    static constexpr float s =
        s_zero        ? 0.0f :
        (4*aq == N)   ? (ss > 0 ? 1.0f : -1.0f) :
        (float)(ss * ct_sin(6.283185307179586476925286766559 * (double)aq / (double)N));
};

template<int P, int N, int SG = 1>
__device__ __forceinline__ float fC(float v, float acc) {
    using T = TW<P, N>;
    constexpr float cc = (SG < 0) ? -T::c : T::c;
    if constexpr (T::c_zero)         return acc;
    else if constexpr (cc ==  1.0f)  return acc + v;
    else if constexpr (cc == -1.0f)  return acc - v;
    else                             return fmaf(v, cc, acc);
}
template<int P, int N, int SG = 1>
__device__ __forceinline__ float fS(float v, float acc) {
    using T = TW<P, N>;
    constexpr float sv = (SG < 0) ? -T::s : T::s;
    if constexpr (T::s_zero)         return acc;
    else if constexpr (sv ==  1.0f)  return acc + v;
    else if constexpr (sv == -1.0f)  return acc - v;
    else                             return fmaf(v, sv, acc);
}

// ---------------- compile-time unroller ----------------
template<int I> struct Ic { static constexpr int v = I; };
template<int I, int E, class F> __device__ __forceinline__ void UNR(F&& f) {
    if constexpr (I < E) { f(Ic<I>{}); UNR<I+1, E>(f); }
}

// ---------------- KA: fused T-DFT + H-DFT  (x -> F2, w-major), w-tile 16, 256 thr ----------------
__global__ void __maxnreg__(112) kA_fwd(const float* __restrict__ x) {
    extern __shared__ float sm[];
    float* Yr = sm;                     // HH*ZSTR floats
    float* Yi = sm + HH*ZSTR;
    const int tid = threadIdx.x;
    const int bc = blockIdx.x / 6;
    const int w0 = (blockIdx.x % 6) * 16;
    const float* xb = x + (size_t)bc * TT * HW + w0;

    const int wl = tid & 15;

    // phase1: T-DFT (real -> complex), folded over t <-> 32-t. 16 hs x 6 passes.
    {
        const int hs = tid >> 4;            // 0..15
        for (int p = 0; p < 6; p++) {
            const int h = p * 16 + hs;
            const float* xp = xb + h * WW + wl;
            float ar[MT], ai[MT];
            float x0  = xp[0];
            float x16 = xp[16 * HW];
            UNR<0,MT>([&](auto K){ constexpr int k = decltype(K)::v;
                ar[k] = (k & 1) ? (x0 - x16) : (x0 + x16);
                ai[k] = 0.0f; });
            UNR<1,16>([&](auto T){ constexpr int t = decltype(T)::v;
                float a = xp[(size_t)t * HW];
                float b = xp[(size_t)(TT - t) * HW];
                float pt = a + b, mt = a - b;
                UNR<0,MT>([&](auto K){ constexpr int k = decltype(K)::v;
                    ar[k] = fC<t*k, TT>(pt, ar[k]);
                    ai[k] = fS<t*k, TT, -1>(mt, ai[k]);
                });
            });
            UNR<0,MT>([&](auto K){ constexpr int k = decltype(K)::v;
                Yr[h*ZSTR + k*16 + wl] = ar[k];
                Yi[h*ZSTR + k*16 + wl] = ai[k]; });
        }
    }
    __syncthreads();

    // phase2: H-DFT (complex), folded over h <-> 96-h. kx split in two halves.
    {
        const int kt   = (tid >> 4) & 7;
        const int half = tid >> 7;
        const float* yr = Yr + kt*16 + wl;
        const float* yi = Yi + kt*16 + wl;
        auto run = [&](auto K0C){
            constexpr int K0 = decltype(K0C)::v;
            float fr[8], fi[8];
            float a0  = yr[0],       b0  = yi[0];
            float a48 = yr[48*ZSTR], b48 = yi[48*ZSTR];
            UNR<0,8>([&](auto J){ constexpr int j = decltype(J)::v; constexpr int kx = K0 + j;
                fr[j] = (kx & 1) ? (a0 - a48) : (a0 + a48);
                fi[j] = (kx & 1) ? (b0 - b48) : (b0 + b48); });
            UNR<1,48>([&](auto H){ constexpr int h = decltype(H)::v;
                float a  = yr[h*ZSTR],      b  = yi[h*ZSTR];
                float a2 = yr[(96-h)*ZSTR], b2 = yi[(96-h)*ZSTR];
                float pa = a + a2, ma = a - a2, pb = b + b2, mb = b - b2;
                UNR<0,8>([&](auto J){ constexpr int j = decltype(J)::v; constexpr int kx = K0 + j;
                    fr[j] = fC<h*kx, HH>(pa, fS<h*kx, HH>(mb, fr[j]));
                    fi[j] = fC<h*kx, HH>(pb, fS<h*kx, HH, -1>(ma, fi[j]));
                });
            });
            size_t base = (size_t)(w0 + wl) * NROW + bc*128 + kt*16 + K0;
            *reinterpret_cast<float4*>(g_F2r + base)     = make_float4(fr[0], fr[1], fr[2], fr[3]);
            *reinterpret_cast<float4*>(g_F2r + base + 4) = make_float4(fr[4], fr[5], fr[6], fr[7]);
            *reinterpret_cast<float4*>(g_F2i + base)     = make_float4(fi[0], fi[1], fi[2], fi[3]);
            *reinterpret_cast<float4*>(g_F2i + base + 4) = make_float4(fi[4], fi[5], fi[6], fi[7]);
        };
        if (half == 0) run(Ic<0>{}); else run(Ic<8>{});
    }
}

// ---------------- K3: W-DFT (F2 -> F3), coalesced, folded over w <-> 96-w ----------------
__global__ void __launch_bounds__(128) k3_wdft() {
    int r = blockIdx.x * 128 + threadIdx.x;       // 32768 rows, exact
    const float* pr = g_F2r + r;
    const float* pi = g_F2i + r;
    float fr[MS], fi[MS];
    {
        float a0  = pr[0],                  b0  = pi[0];
        float a48 = pr[(size_t)48 * NROW],  b48 = pi[(size_t)48 * NROW];
        UNR<0,MS>([&](auto K){ constexpr int ky = decltype(K)::v;
            fr[ky] = (ky & 1) ? (a0 - a48) : (a0 + a48);
            fi[ky] = (ky & 1) ? (b0 - b48) : (b0 + b48); });
    }
    UNR<1,48>([&](auto WI){ constexpr int w = decltype(WI)::v;
        float a  = pr[(size_t)w * NROW],      b  = pi[(size_t)w * NROW];
        float a2 = pr[(size_t)(96-w) * NROW], b2 = pi[(size_t)(96-w) * NROW];
        float pa = a + a2, ma = a - a2, pb = b + b2, mb = b - b2;
        UNR<0,MS>([&](auto K){ constexpr int ky = decltype(K)::v;
            fr[ky] = fC<w*ky, WW>(pa, fS<w*ky, WW>(mb, fr[ky]));
            fi[ky] = fC<w*ky, WW>(pb, fS<w*ky, WW, -1>(ma, fi[ky]));
        });
    });
    size_t o = (size_t)r * MS;
    UNR<0,MS>([&](auto K){ constexpr int ky = decltype(K)::v;
        g_F3r[o + ky] = fr[ky];
        g_F3i[o + ky] = fi[ky]; });
}

// ---------------- K4: channel mix, weights read in ORIGINAL layout ----------------
__global__ void __launch_bounds__(256) k4_mix(const float* __restrict__ wr,
                                              const float* __restrict__ wi) {
    __shared__ float Xr[BC*8], Xi[BC*8];         // 16 KB
    const int m0 = blockIdx.x * 8;
    const int tid = threadIdx.x;
    for (int i = tid; i < BC*8; i += 256) {
        int bcc = i >> 3, mm = i & 7;
        Xr[i] = g_F3r[(size_t)bcc * NMODE + m0 + mm];
        Xi[i] = g_F3i[(size_t)bcc * NMODE + m0 + mm];
    }
    __syncthreads();
    const int d  = tid >> 3;
    const int ml = tid & 7;
    const int m  = m0 + ml;
    const float* wrp = wr + (size_t)d * NMODE + m;
    const float* wip = wi + (size_t)d * NMODE + m;

    float sr[BB], si[BB];
#pragma unroll
    for (int b = 0; b < BB; b++) { sr[b] = 0.0f; si[b] = 0.0f; }

#pragma unroll
    for (int c = 0; c < CC; c++) {
        float a  = wrp[(size_t)c * DD * NMODE];
        float bb = wip[(size_t)c * DD * NMODE];
#pragma unroll
        for (int b = 0; b < BB; b++) {
            float xr = Xr[(b*CC + c)*8 + ml];
            float xi = Xi[(b*CC + c)*8 + ml];
            sr[b] = fmaf(xr, a,  fmaf(-xi, bb, sr[b]));
            si[b] = fmaf(xr, bb, fmaf( xi, a,  si[b]));
        }
    }
    float sc = (((m & (MS-1)) == 0) ? 1.0f : 2.0f) * (1.0f / 294912.0f);
#pragma unroll
    for (int b = 0; b < BB; b++) {
        size_t o = (size_t)(b*DD + d) * NMODE + m;
        g_Sr[o] = sr[b] * sc;
        g_Si[o] = si[b] * sc;
    }
}

// ---------------- KB: fused W-exp + H-exp + T-exp  (S -> out), w-tile 16, 256 thr ----------------
// phase0 transposed: lanes=(kt,kx), w in registers -> all twiddles are FFMA immediates
// (6 constexpr variants on the block's w-group). Transposed back via a small padded
// smem buffer, prefetched to regs before phase1 reuses the staging region for Z.
__global__ void __maxnreg__(112) kB_inv(float* __restrict__ out) {
    extern __shared__ float sm[];
    float* Zr  = sm;                             // HH*ZSTR floats
    float* Zi  = sm + HH*ZSTR;
    float* Ssr = sm;                             // [2048]  staging aliases Z
    float* Ssi = sm + 2048;                      // [2048]
    float* A1r = sm + 4096;                      // [16*A1STR = 2176]
    float* A1i = sm + 4096 + 16*A1STR;           // ends at 8448 < HH*ZSTR

    const int tid = threadIdx.x;
    const int bd = blockIdx.x / 6;
    const int wg = blockIdx.x % 6;
    const int w0 = wg * 16;
    const int wl = tid & 15;
    const int kt = (tid >> 4) & 7;
    const int half = tid >> 7;

    {   // load S tile (coalesced, float4)
        const float4* srp = reinterpret_cast<const float4*>(g_Sr + (size_t)bd * NMODE);
        const float4* sip = reinterpret_cast<const float4*>(g_Si + (size_t)bd * NMODE);
        reinterpret_cast<float4*>(Ssr)[tid]       = srp[tid];
        reinterpret_cast<float4*>(Ssr)[tid + 256] = srp[tid + 256];
        reinterpret_cast<float4*>(Ssi)[tid]       = sip[tid];
        reinterpret_cast<float4*>(Ssi)[tid + 256] = sip[tid + 256];
    }
    __syncthreads();

    // phase0 (128 threads): lane=(kt,kx); compute a1[w0..w0+15] with IMMEDIATE twiddles.
    if (tid < 128) {
        float s_r[MS], s_i[MS];
#pragma unroll
        for (int q = 0; q < 4; q++) {
            float4 vr = reinterpret_cast<const float4*>(Ssr + tid*16)[q];
            float4 vi = reinterpret_cast<const float4*>(Ssi + tid*16)[q];
            s_r[q*4+0] = vr.x; s_r[q*4+1] = vr.y; s_r[q*4+2] = vr.z; s_r[q*4+3] = vr.w;
            s_i[q*4+0] = vi.x; s_i[q*4+1] = vi.y; s_i[q*4+2] = vi.z; s_i[q*4+3] = vi.w;
        }
        const int p_kx = tid & 15;
        float* dr = A1r + p_kx*A1STR + (tid >> 4) * 16;   // [kx][kt*16 + j]
        float* di = A1i + p_kx*A1STR + (tid >> 4) * 16;
        auto run = [&](auto GC){
            constexpr int W0T = decltype(GC)::v * 16;
            float ar[16], ai[16];
            UNR<0,16>([&](auto J){ ar[decltype(J)::v] = 0.f; ai[decltype(J)::v] = 0.f; });
            UNR<0,MS>([&](auto KY){ constexpr int ky = decltype(KY)::v;
                float sv = s_r[ky], iv = s_i[ky];
                UNR<0,16>([&](auto J){ constexpr int j = decltype(J)::v;
                    constexpr int P = ky * (W0T + j);
                    // e^{+i th}: re += sv*c - iv*s ; im += sv*s + iv*c
                    ar[j] = fC<P, WW>(sv, fS<P, WW, -1>(iv, ar[j]));
                    ai[j] = fS<P, WW>(sv, fC<P, WW>(iv, ai[j]));
                });
            });
#pragma unroll
            for (int q = 0; q < 4; q++) {
                reinterpret_cast<float4*>(dr)[q] = make_float4(ar[q*4], ar[q*4+1], ar[q*4+2], ar[q*4+3]);
                reinterpret_cast<float4*>(di)[q] = make_float4(ai[q*4], ai[q*4+1], ai[q*4+2], ai[q*4+3]);
            }
        };
        switch (wg) {
            case 0: run(Ic<0>{}); break;
            case 1: run(Ic<1>{}); break;
            case 2: run(Ic<2>{}); break;
            case 3: run(Ic<3>{}); break;
            case 4: run(Ic<4>{}); break;
            default: run(Ic<5>{}); break;
        }
    }
    __syncthreads();

    // prefetch a1 into registers (conflict-free: banks = 16*kt + wl + 8*kx spread)
    float a1r[MS], a1i[MS];
#pragma unroll
    for (int kx = 0; kx < MS; kx++) {
        a1r[kx] = A1r[kx*A1STR + kt*16 + wl];
        a1i[kx] = A1i[kx*A1STR + kt*16 + wl];
    }
    __syncthreads();   // all staging reads done before Z overwrites

    // phase1: H-expand, folded over output h <-> 96-h; halves split the h range
    {
        auto body = [&](auto H){ constexpr int h = decltype(H)::v;
            float C = 0.f, S = 0.f, C2 = 0.f, S2 = 0.f;
            UNR<0,MS>([&](auto KX){ constexpr int kx = decltype(KX)::v;
                C  = fC<kx*h, HH>(a1r[kx], C);
                C2 = fC<kx*h, HH>(a1i[kx], C2);
                S  = fS<kx*h, HH>(a1i[kx], S);
                S2 = fS<kx*h, HH>(a1r[kx], S2);
            });
            Zr[h*ZSTR + kt*16 + wl] = C - S;
            Zi[h*ZSTR + kt*16 + wl] = C2 + S2;
            if constexpr (h >= 1 && h <= 47) {
                Zr[(96-h)*ZSTR + kt*16 + wl] = C + S;
                Zi[(96-h)*ZSTR + kt*16 + wl] = C2 - S2;
            }
        };
        if (half == 0) UNR<0,25>(body); else UNR<25,49>(body);
    }
    __syncthreads();

    // phase2: T-expand + real part, folded over output t <-> 32-t.
    // lanes = (wl2 w-pair, 32 hs) x 3 passes; float2 loads/stores.
    {
        const int wl2 = tid & 7;
        const int hs  = tid >> 3;           // 0..31
        float* ob = out + (size_t)bd * TT * HW + w0 + wl2*2;
        for (int p = 0; p < 3; p++) {
            const int h = p * 32 + hs;
            float2 zr[MT], zi[MT];
            UNR<0,MT>([&](auto K){ constexpr int k = decltype(K)::v;
                zr[k] = *reinterpret_cast<const float2*>(Zr + h*ZSTR + k*16 + wl2*2);
                zi[k] = *reinterpret_cast<const float2*>(Zi + h*ZSTR + k*16 + wl2*2); });
            float* op = ob + h * WW;
            {   // t = 0 and t = 16
                float2 s0 = make_float2(0.f, 0.f), s16 = make_float2(0.f, 0.f);
                UNR<0,MT>([&](auto K){ constexpr int k = decltype(K)::v;
                    s0.x += zr[k].x; s0.y += zr[k].y;
                    if constexpr (k & 1) { s16.x -= zr[k].x; s16.y -= zr[k].y; }
                    else                 { s16.x += zr[k].x; s16.y += zr[k].y; } });
                *reinterpret_cast<float2*>(op)                    = s0;
                *reinterpret_cast<float2*>(op + (size_t)16 * HW)  = s16;
            }
            UNR<1,16>([&](auto T){ constexpr int t = decltype(T)::v;
                float Cx = 0.f, Cy = 0.f, Sx = 0.f, Sy = 0.f;
                UNR<0,MT>([&](auto K){ constexpr int k = decltype(K)::v;
                    Cx = fC<k*t, TT>(zr[k].x, Cx);
                    Cy = fC<k*t, TT>(zr[k].y, Cy);
                    Sx = fS<k*t, TT>(zi[k].x, Sx);
                    Sy = fS<k*t, TT>(zi[k].y, Sy);
                });
                *reinterpret_cast<float2*>(op + (size_t)t * HW)        = make_float2(Cx - Sx, Cy - Sy);
                *reinterpret_cast<float2*>(op + (size_t)(32 - t) * HW) = make_float2(Cx + Sx, Cy + Sy);
            });
        }
    }
}

// ---------------- launch ----------------
extern "C" void kernel_launch(void* const* d_in, const int* in_sizes, int n_in,
                              void* d_out, int out_size) {
    (void)in_sizes; (void)n_in; (void)out_size;
    const float* x  = (const float*)d_in[0];
    const float* wr = (const float*)d_in[1];
    const float* wi = (const float*)d_in[2];
    float* out = (float*)d_out;

    cudaFuncSetAttribute(kA_fwd, cudaFuncAttributeMaxDynamicSharedMemorySize, SMEM_BYTES);
    cudaFuncSetAttribute(kB_inv, cudaFuncAttributeMaxDynamicSharedMemorySize, SMEM_BYTES);

    kA_fwd <<<1536, 256, SMEM_BYTES>>>(x);    // 256 bc * 6 w-groups
    k3_wdft<<<256,  128>>>();                 // 32768 rows
    k4_mix <<<256,  256>>>(wr, wi);           // 2048 modes / 8 per block
    kB_inv <<<1536, 256, SMEM_BYTES>>>(out);  // 256 bd * 6 w-groups
}

// round 12
// speedup vs baseline: 1.4460x; 1.4460x over previous
#include <cuda_runtime.h>

// Problem constants
#define BB 8
#define CC 32
#define DD 32
#define TT 32
#define HH 96
#define WW 96
#define MT 8
#define MS 16
#define BC (BB*CC)        // 256
#define BD (BB*DD)        // 256
#define HW (HH*WW)        // 9216
#define NMODE (MT*MS*MS)  // 2048
#define NROW (BC*MT*MS)   // 32768 rows of F2
#define TWO_PI 6.28318530717958647692f

// Y/Z smem row stride (floats). 144: h-parity offsets banks by 16 -> phase1/2
// LDS/STS conflict-free. smem = 2*96*144*4 = 110592 B -> 2 CTAs/SM.
#define ZSTR 144
#define SMEM_BYTES (2*HH*ZSTR*4)

// ---------------- scratch (static device globals; no allocation) ----------------
__device__ float g_F2r[WW*NROW];         // after T+H DFT, W-MAJOR: (w, bc*128+kt*16+kx)
__device__ float g_F2i[WW*NROW];
__device__ float g_F3r[BC*NMODE];        // after W-DFT: (bc, m)  m = kt*256+kx*16+ky
__device__ float g_F3i[BC*NMODE];
__device__ float g_Sr [BD*NMODE];        // after mix:   (bd, m)
__device__ float g_Si [BD*NMODE];

// ---------------- compile-time trig (Taylor, double precision) ----------------
__host__ __device__ constexpr double ct_cos(double x) {
    double x2 = x * x, t = 1.0, s = 1.0;
    for (int k = 1; k <= 26; k++) { t *= -x2 / ((2.0*k - 1.0) * (2.0*k)); s += t; }
    return s;
}
__host__ __device__ constexpr double ct_sin(double x) {
    double x2 = x * x, t = x, s = x;
    for (int k = 1; k <= 26; k++) { t *= -x2 / ((2.0*k) * (2.0*k + 1.0)); s += t; }
    return s;
}

// Twiddle cos/sin(2*pi*P/N) with exact 0 / +-1 at quadrant points
template<int P, int N> struct TW {
    static constexpr int    q0 = ((P % N) + N) % N;
    static constexpr int    aq = (q0 > N - q0) ? (N - q0) : q0;
    static constexpr int    ss = (q0 > N/2) ? -1 : 1;
    static constexpr bool c_zero = (4*aq == N);
    static constexpr bool s_zero = (aq == 0) || (2*aq == N);
    static constexpr float c =
        (aq == 0)     ? 1.0f  :
        (2*aq == N)   ? -1.0f :
        c_zero        ? 0.0f  :
        (float)ct_cos(6.283185307179586476925286766559 * (double)aq / (double)N);
    static constexpr float s =
        s_zero        ? 0.0f :
        (4*aq == N)   ? (ss > 0 ? 1.0f : -1.0f) :
        (float)(ss * ct_sin(6.283185307179586476925286766559 * (double)aq / (double)N));
};

template<int P, int N, int SG = 1>
__device__ __forceinline__ float fC(float v, float acc) {
    using T = TW<P, N>;
    constexpr float cc = (SG < 0) ? -T::c : T::c;
    if constexpr (T::c_zero)         return acc;
    else if constexpr (cc ==  1.0f)  return acc + v;
    else if constexpr (cc == -1.0f)  return acc - v;
    else                             return fmaf(v, cc, acc);
}
template<int P, int N, int SG = 1>
__device__ __forceinline__ float fS(float v, float acc) {
    using T = TW<P, N>;
    constexpr float sv = (SG < 0) ? -T::s : T::s;
    if constexpr (T::s_zero)         return acc;
    else if constexpr (sv ==  1.0f)  return acc + v;
    else if constexpr (sv == -1.0f)  return acc - v;
    else                             return fmaf(v, sv, acc);
}

// ---------------- compile-time unroller ----------------
template<int I> struct Ic { static constexpr int v = I; };
template<int I, int E, class F> __device__ __forceinline__ void UNR(F&& f) {
    if constexpr (I < E) { f(Ic<I>{}); UNR<I+1, E>(f); }
}

// ---------------- KA: fused T-DFT + H-DFT  (x -> F2, w-major), w-tile 16, 256 thr ----------------
__global__ void __maxnreg__(112) kA_fwd(const float* __restrict__ x) {
    extern __shared__ float sm[];
    float* Yr = sm;                     // HH*ZSTR floats
    float* Yi = sm + HH*ZSTR;
    const int tid = threadIdx.x;
    const int bc = blockIdx.x / 6;
    const int w0 = (blockIdx.x % 6) * 16;
    const float* xb = x + (size_t)bc * TT * HW + w0;

    const int wl = tid & 15;

    // phase1: T-DFT (real -> complex), folded over t <-> 32-t. 16 hs x 6 passes.
    {
        const int hs = tid >> 4;            // 0..15
        for (int p = 0; p < 6; p++) {
            const int h = p * 16 + hs;
            const float* xp = xb + h * WW + wl;
            float ar[MT], ai[MT];
            float x0  = xp[0];
            float x16 = xp[16 * HW];
            UNR<0,MT>([&](auto K){ constexpr int k = decltype(K)::v;
                ar[k] = (k & 1) ? (x0 - x16) : (x0 + x16);
                ai[k] = 0.0f; });
            UNR<1,16>([&](auto T){ constexpr int t = decltype(T)::v;
                float a = xp[(size_t)t * HW];
                float b = xp[(size_t)(TT - t) * HW];
                float pt = a + b, mt = a - b;
                UNR<0,MT>([&](auto K){ constexpr int k = decltype(K)::v;
                    ar[k] = fC<t*k, TT>(pt, ar[k]);
                    ai[k] = fS<t*k, TT, -1>(mt, ai[k]);
                });
            });
            UNR<0,MT>([&](auto K){ constexpr int k = decltype(K)::v;
                Yr[h*ZSTR + k*16 + wl] = ar[k];
                Yi[h*ZSTR + k*16 + wl] = ai[k]; });
        }
    }
    __syncthreads();

    // phase2: H-DFT (complex), folded over h <-> 96-h. kx split in two halves.
    {
        const int kt   = (tid >> 4) & 7;
        const int half = tid >> 7;
        const float* yr = Yr + kt*16 + wl;
        const float* yi = Yi + kt*16 + wl;
        auto run = [&](auto K0C){
            constexpr int K0 = decltype(K0C)::v;
            float fr[8], fi[8];
            float a0  = yr[0],       b0  = yi[0];
            float a48 = yr[48*ZSTR], b48 = yi[48*ZSTR];
            UNR<0,8>([&](auto J){ constexpr int j = decltype(J)::v; constexpr int kx = K0 + j;
                fr[j] = (kx & 1) ? (a0 - a48) : (a0 + a48);
                fi[j] = (kx & 1) ? (b0 - b48) : (b0 + b48); });
            UNR<1,48>([&](auto H){ constexpr int h = decltype(H)::v;
                float a  = yr[h*ZSTR],      b  = yi[h*ZSTR];
                float a2 = yr[(96-h)*ZSTR], b2 = yi[(96-h)*ZSTR];
                float pa = a + a2, ma = a - a2, pb = b + b2, mb = b - b2;
                UNR<0,8>([&](auto J){ constexpr int j = decltype(J)::v; constexpr int kx = K0 + j;
                    fr[j] = fC<h*kx, HH>(pa, fS<h*kx, HH>(mb, fr[j]));
                    fi[j] = fC<h*kx, HH>(pb, fS<h*kx, HH, -1>(ma, fi[j]));
                });
            });
            size_t base = (size_t)(w0 + wl) * NROW + bc*128 + kt*16 + K0;
            *reinterpret_cast<float4*>(g_F2r + base)     = make_float4(fr[0], fr[1], fr[2], fr[3]);
            *reinterpret_cast<float4*>(g_F2r + base + 4) = make_float4(fr[4], fr[5], fr[6], fr[7]);
            *reinterpret_cast<float4*>(g_F2i + base)     = make_float4(fi[0], fi[1], fi[2], fi[3]);
            *reinterpret_cast<float4*>(g_F2i + base + 4) = make_float4(fi[4], fi[5], fi[6], fi[7]);
        };
        if (half == 0) run(Ic<0>{}); else run(Ic<8>{});
    }
}

// ---------------- K3: W-DFT (F2 -> F3), coalesced, folded over w <-> 96-w ----------------
__global__ void __launch_bounds__(128) k3_wdft() {
    int r = blockIdx.x * 128 + threadIdx.x;       // 32768 rows, exact
    const float* pr = g_F2r + r;
    const float* pi = g_F2i + r;
    float fr[MS], fi[MS];
    {
        float a0  = pr[0],                  b0  = pi[0];
        float a48 = pr[(size_t)48 * NROW],  b48 = pi[(size_t)48 * NROW];
        UNR<0,MS>([&](auto K){ constexpr int ky = decltype(K)::v;
            fr[ky] = (ky & 1) ? (a0 - a48) : (a0 + a48);
            fi[ky] = (ky & 1) ? (b0 - b48) : (b0 + b48); });
    }
    UNR<1,48>([&](auto WI){ constexpr int w = decltype(WI)::v;
        float a  = pr[(size_t)w * NROW],      b  = pi[(size_t)w * NROW];
        float a2 = pr[(size_t)(96-w) * NROW], b2 = pi[(size_t)(96-w) * NROW];
        float pa = a + a2, ma = a - a2, pb = b + b2, mb = b - b2;
        UNR<0,MS>([&](auto K){ constexpr int ky = decltype(K)::v;
            fr[ky] = fC<w*ky, WW>(pa, fS<w*ky, WW>(mb, fr[ky]));
            fi[ky] = fC<w*ky, WW>(pb, fS<w*ky, WW, -1>(ma, fi[ky]));
        });
    });
    size_t o = (size_t)r * MS;
    UNR<0,MS>([&](auto K){ constexpr int ky = decltype(K)::v;
        g_F3r[o + ky] = fr[ky];
        g_F3i[o + ky] = fi[ky]; });
}

// ---------------- K4: channel mix, weights read in ORIGINAL layout ----------------
__global__ void __launch_bounds__(256) k4_mix(const float* __restrict__ wr,
                                              const float* __restrict__ wi) {
    __shared__ float Xr[BC*8], Xi[BC*8];         // 16 KB
    const int m0 = blockIdx.x * 8;
    const int tid = threadIdx.x;
    for (int i = tid; i < BC*8; i += 256) {
        int bcc = i >> 3, mm = i & 7;
        Xr[i] = g_F3r[(size_t)bcc * NMODE + m0 + mm];
        Xi[i] = g_F3i[(size_t)bcc * NMODE + m0 + mm];
    }
    __syncthreads();
    const int d  = tid >> 3;
    const int ml = tid & 7;
    const int m  = m0 + ml;
    const float* wrp = wr + (size_t)d * NMODE + m;
    const float* wip = wi + (size_t)d * NMODE + m;

    float sr[BB], si[BB];
#pragma unroll
    for (int b = 0; b < BB; b++) { sr[b] = 0.0f; si[b] = 0.0f; }

#pragma unroll
    for (int c = 0; c < CC; c++) {
        float a  = wrp[(size_t)c * DD * NMODE];
        float bb = wip[(size_t)c * DD * NMODE];
#pragma unroll
        for (int b = 0; b < BB; b++) {
            float xr = Xr[(b*CC + c)*8 + ml];
            float xi = Xi[(b*CC + c)*8 + ml];
            sr[b] = fmaf(xr, a,  fmaf(-xi, bb, sr[b]));
            si[b] = fmaf(xr, bb, fmaf( xi, a,  si[b]));
        }
    }
    float sc = (((m & (MS-1)) == 0) ? 1.0f : 2.0f) * (1.0f / 294912.0f);
#pragma unroll
    for (int b = 0; b < BB; b++) {
        size_t o = (size_t)(b*DD + d) * NMODE + m;
        g_Sr[o] = sr[b] * sc;
        g_Si[o] = si[b] * sc;
    }
}

// ---------------- KB: fused W-exp + H-exp + T-exp  (S -> out), w-tile 16, 256 thr ----------------
// R10 structure (all 256 threads in phase0, runtime tab twiddles) with float4 LDS
// in phase0 and float2 phase2.
__global__ void __maxnreg__(112) kB_inv(float* __restrict__ out) {
    extern __shared__ float sm[];
    float* Zr  = sm;                             // HH*ZSTR floats
    float* Zi  = sm + HH*ZSTR;
    float*  Ssr = sm;                            // phase0 staging aliases Z
    float*  Ssi = sm + 2048;
    float2* tab = reinterpret_cast<float2*>(sm + 4096);   // [ky][wl] 256 float2

    const int tid = threadIdx.x;
    const int bd = blockIdx.x / 6;
    const int w0 = (blockIdx.x % 6) * 16;
    const int wl = tid & 15;
    const int kt = (tid >> 4) & 7;
    const int half = tid >> 7;

    {   // load S tile (coalesced, float4) + per-block w table
        const float4* srp = reinterpret_cast<const float4*>(g_Sr + (size_t)bd * NMODE);
        const float4* sip = reinterpret_cast<const float4*>(g_Si + (size_t)bd * NMODE);
        reinterpret_cast<float4*>(Ssr)[tid]       = srp[tid];
        reinterpret_cast<float4*>(Ssr)[tid + 256] = srp[tid + 256];
        reinterpret_cast<float4*>(Ssi)[tid]       = sip[tid];
        reinterpret_cast<float4*>(Ssi)[tid + 256] = sip[tid + 256];
        {
            int ky = tid >> 4, wl2 = tid & 15;
            float ssin, ccos;
            sincosf(TWO_PI * (float)((ky * (w0 + wl2)) % WW) / (float)WW, &ssin, &ccos);
            tab[tid] = make_float2(ccos, ssin);
        }
    }
    __syncthreads();

    // phase0: W-expand into registers, all 16 kx per thread, e^{+i 2pi ky w / 96}.
    // ky-contiguous float4 LDS (8 LDS.128 per kx instead of 32 LDS.32).
    float a1r[MS], a1i[MS];
    {
        float ec[MS], es[MS];
#pragma unroll
        for (int ky = 0; ky < MS; ky++) { float2 e = tab[ky*16 + wl]; ec[ky] = e.x; es[ky] = e.y; }
#pragma unroll
        for (int kx = 0; kx < MS; kx++) {
            const float4* pr4 = reinterpret_cast<const float4*>(Ssr + (kt*MS + kx) * MS);
            const float4* pi4 = reinterpret_cast<const float4*>(Ssi + (kt*MS + kx) * MS);
            float rr = 0.f, ii = 0.f;
#pragma unroll
            for (int q = 0; q < 4; q++) {
                float4 vr = pr4[q];
                float4 vi = pi4[q];
                rr = fmaf(vr.x, ec[q*4+0], fmaf(-vi.x, es[q*4+0], rr));
                ii = fmaf(vr.x, es[q*4+0], fmaf( vi.x, ec[q*4+0], ii));
                rr = fmaf(vr.y, ec[q*4+1], fmaf(-vi.y, es[q*4+1], rr));
                ii = fmaf(vr.y, es[q*4+1], fmaf( vi.y, ec[q*4+1], ii));
                rr = fmaf(vr.z, ec[q*4+2], fmaf(-vi.z, es[q*4+2], rr));
                ii = fmaf(vr.z, es[q*4+2], fmaf( vi.z, ec[q*4+2], ii));
                rr = fmaf(vr.w, ec[q*4+3], fmaf(-vi.w, es[q*4+3], rr));
                ii = fmaf(vr.w, es[q*4+3], fmaf( vi.w, ec[q*4+3], ii));
            }
            a1r[kx] = rr; a1i[kx] = ii;
        }
    }
    __syncthreads();   // staging reads done before Z overwrites

    // phase1: H-expand, folded over output h <-> 96-h; halves split the h range
    {
        auto body = [&](auto H){ constexpr int h = decltype(H)::v;
            float C = 0.f, S = 0.f, C2 = 0.f, S2 = 0.f;
            UNR<0,MS>([&](auto KX){ constexpr int kx = decltype(KX)::v;
                C  = fC<kx*h, HH>(a1r[kx], C);
                C2 = fC<kx*h, HH>(a1i[kx], C2);
                S  = fS<kx*h, HH>(a1i[kx], S);
                S2 = fS<kx*h, HH>(a1r[kx], S2);
            });
            Zr[h*ZSTR + kt*16 + wl] = C - S;
            Zi[h*ZSTR + kt*16 + wl] = C2 + S2;
            if constexpr (h >= 1 && h <= 47) {
                Zr[(96-h)*ZSTR + kt*16 + wl] = C + S;
                Zi[(96-h)*ZSTR + kt*16 + wl] = C2 - S2;
            }
        };
        if (half == 0) UNR<0,25>(body); else UNR<25,49>(body);
    }
    __syncthreads();

    // phase2: T-expand + real part, folded over output t <-> 32-t.
    // lanes = (wl2 w-pair, 32 hs) x 3 passes; float2 loads/stores.
    {
        const int wl2 = tid & 7;
        const int hs  = tid >> 3;           // 0..31
        float* ob = out + (size_t)bd * TT * HW + w0 + wl2*2;
        for (int p = 0; p < 3; p++) {
            const int h = p * 32 + hs;
            float2 zr[MT], zi[MT];
            UNR<0,MT>([&](auto K){ constexpr int k = decltype(K)::v;
                zr[k] = *reinterpret_cast<const float2*>(Zr + h*ZSTR + k*16 + wl2*2);
                zi[k] = *reinterpret_cast<const float2*>(Zi + h*ZSTR + k*16 + wl2*2); });
            float* op = ob + h * WW;
            {   // t = 0 and t = 16
                float2 s0 = make_float2(0.f, 0.f), s16 = make_float2(0.f, 0.f);
                UNR<0,MT>([&](auto K){ constexpr int k = decltype(K)::v;
                    s0.x += zr[k].x; s0.y += zr[k].y;
                    if constexpr (k & 1) { s16.x -= zr[k].x; s16.y -= zr[k].y; }
                    else                 { s16.x += zr[k].x; s16.y += zr[k].y; } });
                *reinterpret_cast<float2*>(op)                    = s0;
                *reinterpret_cast<float2*>(op + (size_t)16 * HW)  = s16;
            }
            UNR<1,16>([&](auto T){ constexpr int t = decltype(T)::v;
                float Cx = 0.f, Cy = 0.f, Sx = 0.f, Sy = 0.f;
                UNR<0,MT>([&](auto K){ constexpr int k = decltype(K)::v;
                    Cx = fC<k*t, TT>(zr[k].x, Cx);
                    Cy = fC<k*t, TT>(zr[k].y, Cy);
                    Sx = fS<k*t, TT>(zi[k].x, Sx);
                    Sy = fS<k*t, TT>(zi[k].y, Sy);
                });
                *reinterpret_cast<float2*>(op + (size_t)t * HW)        = make_float2(Cx - Sx, Cy - Sy);
                *reinterpret_cast<float2*>(op + (size_t)(32 - t) * HW) = make_float2(Cx + Sx, Cy + Sy);
            });
        }
    }
}

// ---------------- launch ----------------
extern "C" void kernel_launch(void* const* d_in, const int* in_sizes, int n_in,
                              void* d_out, int out_size) {
    (void)in_sizes; (void)n_in; (void)out_size;
    const float* x  = (const float*)d_in[0];
    const float* wr = (const float*)d_in[1];
    const float* wi = (const float*)d_in[2];
    float* out = (float*)d_out;

    cudaFuncSetAttribute(kA_fwd, cudaFuncAttributeMaxDynamicSharedMemorySize, SMEM_BYTES);
    cudaFuncSetAttribute(kB_inv, cudaFuncAttributeMaxDynamicSharedMemorySize, SMEM_BYTES);

    kA_fwd <<<1536, 256, SMEM_BYTES>>>(x);    // 256 bc * 6 w-groups
    k3_wdft<<<256,  128>>>();                 // 32768 rows
    k4_mix <<<256,  256>>>(wr, wi);           // 2048 modes / 8 per block
    kB_inv <<<1536, 256, SMEM_BYTES>>>(out);  // 256 bd * 6 w-groups
}

// round 13
// speedup vs baseline: 1.5765x; 1.0902x over previous
#include <cuda_runtime.h>

// Problem constants
#define BB 8
#define CC 32
#define DD 32
#define TT 32
#define HH 96
#define WW 96
#define MT 8
#define MS 16
#define BC (BB*CC)        // 256
#define BD (BB*DD)        // 256
#define HW (HH*WW)        // 9216
#define NMODE (MT*MS*MS)  // 2048
#define NROW (BC*MT*MS)   // 32768 rows of F2
#define TWO_PI 6.28318530717958647692f

// Y/Z smem row stride (floats). 144: conflict-free in all phases.
#define ZSTR 144
#define SMEM_BYTES (2*HH*ZSTR*4)

// ---------------- scratch (static device globals; no allocation) ----------------
__device__ float g_F2r[WW*NROW];         // after T+H DFT, W-MAJOR: (w, bc*128+kt*16+kx)
__device__ float g_F2i[WW*NROW];
__device__ float g_F3r[BC*NMODE];        // after W-DFT: (bc, m)  m = kt*256+kx*16+ky
__device__ float g_F3i[BC*NMODE];
__device__ float g_Sr [BD*NMODE];        // after mix:   (bd, m)
__device__ float g_Si [BD*NMODE];

// ---------------- compile-time trig (Taylor, double precision) ----------------
__host__ __device__ constexpr double ct_cos(double x) {
    double x2 = x * x, t = 1.0, s = 1.0;
    for (int k = 1; k <= 26; k++) { t *= -x2 / ((2.0*k - 1.0) * (2.0*k)); s += t; }
    return s;
}
__host__ __device__ constexpr double ct_sin(double x) {
    double x2 = x * x, t = x, s = x;
    for (int k = 1; k <= 26; k++) { t *= -x2 / ((2.0*k) * (2.0*k + 1.0)); s += t; }
    return s;
}

// Twiddle cos/sin(2*pi*P/N) with exact 0 / +-1 at quadrant points
template<int P, int N> struct TW {
    static constexpr int    q0 = ((P % N) + N) % N;
    static constexpr int    aq = (q0 > N - q0) ? (N - q0) : q0;
    static constexpr int    ss = (q0 > N/2) ? -1 : 1;
    static constexpr bool c_zero = (4*aq == N);
    static constexpr bool s_zero = (aq == 0) || (2*aq == N);
    static constexpr float c =
        (aq == 0)     ? 1.0f  :
        (2*aq == N)   ? -1.0f :
        c_zero        ? 0.0f  :
        (float)ct_cos(6.283185307179586476925286766559 * (double)aq / (double)N);
    static constexpr float s =
        s_zero        ? 0.0f :
        (4*aq == N)   ? (ss > 0 ? 1.0f : -1.0f) :
        (float)(ss * ct_sin(6.283185307179586476925286766559 * (double)aq / (double)N));
};

template<int P, int N, int SG = 1>
__device__ __forceinline__ float fC(float v, float acc) {
    using T = TW<P, N>;
    constexpr float cc = (SG < 0) ? -T::c : T::c;
    if constexpr (T::c_zero)         return acc;
    else if constexpr (cc ==  1.0f)  return acc + v;
    else if constexpr (cc == -1.0f)  return acc - v;
    else                             return fmaf(v, cc, acc);
}
template<int P, int N, int SG = 1>
__device__ __forceinline__ float fS(float v, float acc) {
    using T = TW<P, N>;
    constexpr float sv = (SG < 0) ? -T::s : T::s;
    if constexpr (T::s_zero)         return acc;
    else if constexpr (sv ==  1.0f)  return acc + v;
    else if constexpr (sv == -1.0f)  return acc - v;
    else                             return fmaf(v, sv, acc);
}

// ---------------- compile-time unroller ----------------
template<int I> struct Ic { static constexpr int v = I; };
template<int I, int E, class F> __device__ __forceinline__ void UNR(F&& f) {
    if constexpr (I < E) { f(Ic<I>{}); UNR<I+1, E>(f); }
}

// ---------------- KA: fused T-DFT + H-DFT  (x -> F2, w-major), radix-2 folds ----------------
__global__ void __maxnreg__(112) kA_fwd(const float* __restrict__ x) {
    extern __shared__ float sm[];
    float* Yr = sm;                     // HH*ZSTR floats
    float* Yi = sm + HH*ZSTR;
    const int tid = threadIdx.x;
    const int bc = blockIdx.x / 6;
    const int w0 = (blockIdx.x % 6) * 16;
    const float* xb = x + (size_t)bc * TT * HW + w0;

    const int wl = tid & 15;

    // phase1: T-DFT (real -> complex). Input fold x[t] +- x[t+16] -> even/odd kt
    // banks, then t <-> 16-t mirror (cos-sym for even kt, anti for odd).
    {
        const int hs = tid >> 4;            // 0..15
        for (int p = 0; p < 6; p++) {
            const int h = p * 16 + hs;
            const float* xp = xb + h * WW + wl;
            float xe[16], xo[16];
            UNR<0,16>([&](auto T){ constexpr int t = decltype(T)::v;
                float a = xp[(size_t)t * HW];
                float b = xp[(size_t)(t + 16) * HW];
                xe[t] = a + b; xo[t] = a - b; });
            float ar[MT], ai[MT];
            UNR<0,MT>([&](auto K){ constexpr int k = decltype(K)::v;
                if constexpr ((k & 1) == 0) {
                    ar[k] = fC<k*8, TT>(xe[8], xe[0]);   // t=0 (c=1) + t=8 (c=+-1)
                    ai[k] = 0.0f;                        // sin terms vanish at t=0,8
                } else {
                    ar[k] = xo[0];                       // t=0 c=1; t=8 c=0
                    ai[k] = fS<k*8, TT, -1>(xo[8], 0.0f);
                }
            });
            UNR<1,8>([&](auto T){ constexpr int t = decltype(T)::v;
                float pe = xe[t] + xe[16-t], me = xe[t] - xe[16-t];
                float po = xo[t] + xo[16-t], mo = xo[t] - xo[16-t];
                UNR<0,MT>([&](auto K){ constexpr int k = decltype(K)::v;
                    if constexpr ((k & 1) == 0) {
                        ar[k] = fC<k*t, TT>(pe, ar[k]);
                        ai[k] = fS<k*t, TT, -1>(me, ai[k]);
                    } else {
                        ar[k] = fC<k*t, TT>(mo, ar[k]);
                        ai[k] = fS<k*t, TT, -1>(po, ai[k]);
                    }
                });
            });
            UNR<0,MT>([&](auto K){ constexpr int k = decltype(K)::v;
                Yr[h*ZSTR + k*16 + wl] = ar[k];
                Yi[h*ZSTR + k*16 + wl] = ai[k]; });
        }
    }
    __syncthreads();

    // phase2: H-DFT. u=y[h]+y[h+48] -> even kx, v=y[h]-y[h+48] -> odd kx;
    // then 48-domain mirror h <-> 48-h. kx split in two halves.
    {
        const int kt   = (tid >> 4) & 7;
        const int half = tid >> 7;
        const float* yr = Yr + kt*16 + wl;
        const float* yi = Yi + kt*16 + wl;
        auto run = [&](auto K0C){
            constexpr int K0 = decltype(K0C)::v;
            float fr[8], fi[8];
            {   // self-paired points: rows {0,48} and {24,72}
                float y0r = yr[0],       y0i = yi[0];
                float y48r = yr[48*ZSTR], y48i = yi[48*ZSTR];
                float y24r = yr[24*ZSTR], y24i = yi[24*ZSTR];
                float y72r = yr[72*ZSTR], y72i = yi[72*ZSTR];
                float u0r = y0r + y48r,  u0i = y0i + y48i;
                float v0r = y0r - y48r,  v0i = y0i - y48i;
                float u24r = y24r + y72r, u24i = y24i + y72i;
                float v24r = y24r - y72r, v24i = y24i - y72i;
                UNR<0,8>([&](auto J){ constexpr int j = decltype(J)::v; constexpr int kx = K0 + j;
                    if constexpr ((kx & 1) == 0) {
                        fr[j] = fC<kx*24, HH>(u24r, u0r);
                        fi[j] = fC<kx*24, HH>(u24i, u0i);
                    } else {
                        fr[j] = fS<kx*24, HH>(v24i, v0r);
                        fi[j] = fS<kx*24, HH, -1>(v24r, v0i);
                    }
                });
            }
            UNR<1,24>([&](auto H){ constexpr int h = decltype(H)::v;
                float yar = yr[h*ZSTR],      yai = yi[h*ZSTR];       // h
                float ybr = yr[(96-h)*ZSTR], ybi = yi[(96-h)*ZSTR];  // 96-h
                float ycr = yr[(48+h)*ZSTR], yci = yi[(48+h)*ZSTR];  // 48+h
                float ydr = yr[(48-h)*ZSTR], ydi = yi[(48-h)*ZSTR];  // 48-h
                // even bank: u[h]=a+c, u[48-h]=d+b; mirror: cos keeps, sin flips
                float uar = yar + ycr, uai = yai + yci;
                float ubr = ydr + ybr, ubi = ydi + ybi;
                float pa = uar + ubr, ma = uar - ubr;
                float pb = uai + ubi, mb = uai - ubi;
                // odd bank: v[h]=a-c, v[48-h]=d-b; mirror: cos flips, sin keeps
                float var_ = yar - ycr, vai = yai - yci;
                float vbr  = ydr - ybr, vbi = ydi - ybi;
                float qa = var_ - vbr, qm = var_ + vbr;
                float qb = vai - vbi,  qp = vai + vbi;
                UNR<0,8>([&](auto J){ constexpr int j = decltype(J)::v; constexpr int kx = K0 + j;
                    if constexpr ((kx & 1) == 0) {
                        fr[j] = fC<kx*h, HH>(pa, fS<kx*h, HH>(mb, fr[j]));
                        fi[j] = fC<kx*h, HH>(pb, fS<kx*h, HH, -1>(ma, fi[j]));
                    } else {
                        fr[j] = fC<kx*h, HH>(qa, fS<kx*h, HH>(qp, fr[j]));
                        fi[j] = fC<kx*h, HH>(qb, fS<kx*h, HH, -1>(qm, fi[j]));
                    }
                });
            });
            size_t base = (size_t)(w0 + wl) * NROW + bc*128 + kt*16 + K0;
            *reinterpret_cast<float4*>(g_F2r + base)     = make_float4(fr[0], fr[1], fr[2], fr[3]);
            *reinterpret_cast<float4*>(g_F2r + base + 4) = make_float4(fr[4], fr[5], fr[6], fr[7]);
            *reinterpret_cast<float4*>(g_F2i + base)     = make_float4(fi[0], fi[1], fi[2], fi[3]);
            *reinterpret_cast<float4*>(g_F2i + base + 4) = make_float4(fi[4], fi[5], fi[6], fi[7]);
        };
        if (half == 0) run(Ic<0>{}); else run(Ic<8>{});
    }
}

// ---------------- K3: W-DFT (F2 -> F3), coalesced, folded over w <-> 96-w ----------------
__global__ void __launch_bounds__(128) k3_wdft() {
    int r = blockIdx.x * 128 + threadIdx.x;       // 32768 rows, exact
    const float* pr = g_F2r + r;
    const float* pi = g_F2i + r;
    float fr[MS], fi[MS];
    {
        float a0  = pr[0],                  b0  = pi[0];
        float a48 = pr[(size_t)48 * NROW],  b48 = pi[(size_t)48 * NROW];
        UNR<0,MS>([&](auto K){ constexpr int ky = decltype(K)::v;
            fr[ky] = (ky & 1) ? (a0 - a48) : (a0 + a48);
            fi[ky] = (ky & 1) ? (b0 - b48) : (b0 + b48); });
    }
    UNR<1,48>([&](auto WI){ constexpr int w = decltype(WI)::v;
        float a  = pr[(size_t)w * NROW],      b  = pi[(size_t)w * NROW];
        float a2 = pr[(size_t)(96-w) * NROW], b2 = pi[(size_t)(96-w) * NROW];
        float pa = a + a2, ma = a - a2, pb = b + b2, mb = b - b2;
        UNR<0,MS>([&](auto K){ constexpr int ky = decltype(K)::v;
            fr[ky] = fC<w*ky, WW>(pa, fS<w*ky, WW>(mb, fr[ky]));
            fi[ky] = fC<w*ky, WW>(pb, fS<w*ky, WW, -1>(ma, fi[ky]));
        });
    });
    size_t o = (size_t)r * MS;
    UNR<0,MS>([&](auto K){ constexpr int ky = decltype(K)::v;
        g_F3r[o + ky] = fr[ky];
        g_F3i[o + ky] = fi[ky]; });
}

// ---------------- K4: channel mix, weights read in ORIGINAL layout ----------------
__global__ void __launch_bounds__(256) k4_mix(const float* __restrict__ wr,
                                              const float* __restrict__ wi) {
    __shared__ float Xr[BC*8], Xi[BC*8];         // 16 KB
    const int m0 = blockIdx.x * 8;
    const int tid = threadIdx.x;
    for (int i = tid; i < BC*8; i += 256) {
        int bcc = i >> 3, mm = i & 7;
        Xr[i] = g_F3r[(size_t)bcc * NMODE + m0 + mm];
        Xi[i] = g_F3i[(size_t)bcc * NMODE + m0 + mm];
    }
    __syncthreads();
    const int d  = tid >> 3;
    const int ml = tid & 7;
    const int m  = m0 + ml;
    const float* wrp = wr + (size_t)d * NMODE + m;
    const float* wip = wi + (size_t)d * NMODE + m;

    float sr[BB], si[BB];
#pragma unroll
    for (int b = 0; b < BB; b++) { sr[b] = 0.0f; si[b] = 0.0f; }

#pragma unroll
    for (int c = 0; c < CC; c++) {
        float a  = wrp[(size_t)c * DD * NMODE];
        float bb = wip[(size_t)c * DD * NMODE];
#pragma unroll
        for (int b = 0; b < BB; b++) {
            float xr = Xr[(b*CC + c)*8 + ml];
            float xi = Xi[(b*CC + c)*8 + ml];
            sr[b] = fmaf(xr, a,  fmaf(-xi, bb, sr[b]));
            si[b] = fmaf(xr, bb, fmaf( xi, a,  si[b]));
        }
    }
    float sc = (((m & (MS-1)) == 0) ? 1.0f : 2.0f) * (1.0f / 294912.0f);
#pragma unroll
    for (int b = 0; b < BB; b++) {
        size_t o = (size_t)(b*DD + d) * NMODE + m;
        g_Sr[o] = sr[b] * sc;
        g_Si[o] = si[b] * sc;
    }
}

// ---------------- KB: fused W-exp + H-exp + T-exp  (S -> out), radix-2 folds ----------------
__global__ void __maxnreg__(112) kB_inv(float* __restrict__ out) {
    extern __shared__ float sm[];
    float* Zr  = sm;                             // HH*ZSTR floats
    float* Zi  = sm + HH*ZSTR;
    float*  Ssr = sm;                            // phase0 staging aliases Z
    float*  Ssi = sm + 2048;
    float2* tab = reinterpret_cast<float2*>(sm + 4096);   // [ky][wl] 256 float2

    const int tid = threadIdx.x;
    const int bd = blockIdx.x / 6;
    const int w0 = (blockIdx.x % 6) * 16;
    const int wl = tid & 15;
    const int kt = (tid >> 4) & 7;
    const int half = tid >> 7;

    {   // load S tile (coalesced, float4) + per-block w table
        const float4* srp = reinterpret_cast<const float4*>(g_Sr + (size_t)bd * NMODE);
        const float4* sip = reinterpret_cast<const float4*>(g_Si + (size_t)bd * NMODE);
        reinterpret_cast<float4*>(Ssr)[tid]       = srp[tid];
        reinterpret_cast<float4*>(Ssr)[tid + 256] = srp[tid + 256];
        reinterpret_cast<float4*>(Ssi)[tid]       = sip[tid];
        reinterpret_cast<float4*>(Ssi)[tid + 256] = sip[tid + 256];
        {
            int ky = tid >> 4, wl2 = tid & 15;
            float ssin, ccos;
            sincosf(TWO_PI * (float)((ky * (w0 + wl2)) % WW) / (float)WW, &ssin, &ccos);
            tab[tid] = make_float2(ccos, ssin);
        }
    }
    __syncthreads();

    // phase0: W-expand into registers, all 16 kx per thread, e^{+i 2pi ky w / 96}.
    float a1r[MS], a1i[MS];
    {
        float ec[MS], es[MS];
#pragma unroll
        for (int ky = 0; ky < MS; ky++) { float2 e = tab[ky*16 + wl]; ec[ky] = e.x; es[ky] = e.y; }
#pragma unroll
        for (int kx = 0; kx < MS; kx++) {
            const float4* pr4 = reinterpret_cast<const float4*>(Ssr + (kt*MS + kx) * MS);
            const float4* pi4 = reinterpret_cast<const float4*>(Ssi + (kt*MS + kx) * MS);
            float rr = 0.f, ii = 0.f;
#pragma unroll
            for (int q = 0; q < 4; q++) {
                float4 vr = pr4[q];
                float4 vi = pi4[q];
                rr = fmaf(vr.x, ec[q*4+0], fmaf(-vi.x, es[q*4+0], rr));
                ii = fmaf(vr.x, es[q*4+0], fmaf( vi.x, ec[q*4+0], ii));
                rr = fmaf(vr.y, ec[q*4+1], fmaf(-vi.y, es[q*4+1], rr));
                ii = fmaf(vr.y, es[q*4+1], fmaf( vi.y, ec[q*4+1], ii));
                rr = fmaf(vr.z, ec[q*4+2], fmaf(-vi.z, es[q*4+2], rr));
                ii = fmaf(vr.z, es[q*4+2], fmaf( vi.z, ec[q*4+2], ii));
                rr = fmaf(vr.w, ec[q*4+3], fmaf(-vi.w, es[q*4+3], rr));
                ii = fmaf(vr.w, es[q*4+3], fmaf( vi.w, ec[q*4+3], ii));
            }
            a1r[kx] = rr; a1i[kx] = ii;
        }
    }
    __syncthreads();   // staging reads done before Z overwrites

    // phase1: H-expand with quad fold {h, 96-h, 48+h, 48-h} via even/odd kx chains.
    {
        auto quad = [&](auto H){ constexpr int h = decltype(H)::v;
            float Ce=0.f, Co=0.f, Se=0.f, So=0.f, C2e=0.f, C2o=0.f, S2e=0.f, S2o=0.f;
            UNR<0,8>([&](auto E){ constexpr int kx = 2 * decltype(E)::v;
                Ce  = fC<kx*h, HH>(a1r[kx], Ce);
                C2e = fC<kx*h, HH>(a1i[kx], C2e);
                Se  = fS<kx*h, HH>(a1i[kx], Se);
                S2e = fS<kx*h, HH>(a1r[kx], S2e);
            });
            UNR<0,8>([&](auto O){ constexpr int kx = 2 * decltype(O)::v + 1;
                Co  = fC<kx*h, HH>(a1r[kx], Co);
                C2o = fC<kx*h, HH>(a1i[kx], C2o);
                So  = fS<kx*h, HH>(a1i[kx], So);
                S2o = fS<kx*h, HH>(a1r[kx], S2o);
            });
            float Cp = Ce+Co, Cm = Ce-Co, Sp = Se+So, Sm = Se-So;
            float C2p = C2e+C2o, C2m = C2e-C2o, S2p = S2e+S2o, S2m = S2e-S2o;
            Zr[h*ZSTR + kt*16 + wl]      = Cp - Sp;
            Zi[h*ZSTR + kt*16 + wl]      = C2p + S2p;
            Zr[(96-h)*ZSTR + kt*16 + wl] = Cp + Sp;
            Zi[(96-h)*ZSTR + kt*16 + wl] = C2p - S2p;
            Zr[(48+h)*ZSTR + kt*16 + wl] = Cm - Sm;
            Zi[(48+h)*ZSTR + kt*16 + wl] = C2m + S2m;
            Zr[(48-h)*ZSTR + kt*16 + wl] = Cm + Sm;
            Zi[(48-h)*ZSTR + kt*16 + wl] = C2m - S2m;
        };
        if (half == 0) {
            {   // self points {0, 48}: c=1 / c=(-1)^kx, s=0
                float s0r=0.f, s0i=0.f, s48r=0.f, s48i=0.f;
                UNR<0,MS>([&](auto K){ constexpr int kx = decltype(K)::v;
                    s0r += a1r[kx]; s0i += a1i[kx];
                    if constexpr (kx & 1) { s48r -= a1r[kx]; s48i -= a1i[kx]; }
                    else                  { s48r += a1r[kx]; s48i += a1i[kx]; } });
                Zr[0*ZSTR + kt*16 + wl]  = s0r;  Zi[0*ZSTR + kt*16 + wl]  = s0i;
                Zr[48*ZSTR + kt*16 + wl] = s48r; Zi[48*ZSTR + kt*16 + wl] = s48i;
            }
            UNR<1,13>(quad);
        } else {
            UNR<13,25>(quad);   // h=24 quad writes rows 24/72 twice with equal values (benign)
        }
    }
    __syncthreads();

    // phase2: T-expand + real part, quad fold {t, 32-t, 16+t, 16-t}; float2 lanes.
    {
        const int wl2 = tid & 7;
        const int hs  = tid >> 3;           // 0..31
        float* ob = out + (size_t)bd * TT * HW + w0 + wl2*2;
        for (int p = 0; p < 3; p++) {
            const int h = p * 32 + hs;
            float2 zr[MT], zi[MT];
            UNR<0,MT>([&](auto K){ constexpr int k = decltype(K)::v;
                zr[k] = *reinterpret_cast<const float2*>(Zr + h*ZSTR + k*16 + wl2*2);
                zi[k] = *reinterpret_cast<const float2*>(Zi + h*ZSTR + k*16 + wl2*2); });
            float* op = ob + h * WW;
            {   // t = 0 and t = 16
                float2 s0 = make_float2(0.f, 0.f), s16 = make_float2(0.f, 0.f);
                UNR<0,MT>([&](auto K){ constexpr int k = decltype(K)::v;
                    s0.x += zr[k].x; s0.y += zr[k].y;
                    if constexpr (k & 1) { s16.x -= zr[k].x; s16.y -= zr[k].y; }
                    else                 { s16.x += zr[k].x; s16.y += zr[k].y; } });
                *reinterpret_cast<float2*>(op)                    = s0;
                *reinterpret_cast<float2*>(op + (size_t)16 * HW)  = s16;
            }
            {   // t = 8 and t = 24: cos nonzero for even k, sin nonzero for odd k
                float Cex=0.f, Cey=0.f, Sox=0.f, Soy=0.f;
                UNR<0,4>([&](auto E){ constexpr int k = 2 * decltype(E)::v;
                    Cex = fC<k*8, TT>(zr[k].x, Cex);
                    Cey = fC<k*8, TT>(zr[k].y, Cey); });
                UNR<0,4>([&](auto O){ constexpr int k = 2 * decltype(O)::v + 1;
                    Sox = fS<k*8, TT>(zi[k].x, Sox);
                    Soy = fS<k*8, TT>(zi[k].y, Soy); });
                *reinterpret_cast<float2*>(op + (size_t)8  * HW) = make_float2(Cex - Sox, Cey - Soy);
                *reinterpret_cast<float2*>(op + (size_t)24 * HW) = make_float2(Cex + Sox, Cey + Soy);
            }
            UNR<1,8>([&](auto T){ constexpr int t = decltype(T)::v;
                float Cex=0.f, Cey=0.f, Cox=0.f, Coy=0.f;
                float Sex=0.f, Sey=0.f, Sox=0.f, Soy=0.f;
                UNR<0,4>([&](auto E){ constexpr int k = 2 * decltype(E)::v;
                    Cex = fC<k*t, TT>(zr[k].x, Cex);
                    Cey = fC<k*t, TT>(zr[k].y, Cey);
                    Sex = fS<k*t, TT>(zi[k].x, Sex);
                    Sey = fS<k*t, TT>(zi[k].y, Sey); });
                UNR<0,4>([&](auto O){ constexpr int k = 2 * decltype(O)::v + 1;
                    Cox = fC<k*t, TT>(zr[k].x, Cox);
                    Coy = fC<k*t, TT>(zr[k].y, Coy);
                    Sox = fS<k*t, TT>(zi[k].x, Sox);
                    Soy = fS<k*t, TT>(zi[k].y, Soy); });
                float Cpx = Cex+Cox, Cpy = Cey+Coy, Cmx = Cex-Cox, Cmy = Cey-Coy;
                float Spx = Sex+Sox, Spy = Sey+Soy, Smx = Sex-Sox, Smy = Sey-Soy;
                *reinterpret_cast<float2*>(op + (size_t)t * HW)        = make_float2(Cpx - Spx, Cpy - Spy);
                *reinterpret_cast<float2*>(op + (size_t)(32 - t) * HW) = make_float2(Cpx + Spx, Cpy + Spy);
                *reinterpret_cast<float2*>(op + (size_t)(16 + t) * HW) = make_float2(Cmx - Smx, Cmy - Smy);
                *reinterpret_cast<float2*>(op + (size_t)(16 - t) * HW) = make_float2(Cmx + Smx, Cmy + Smy);
            });
        }
    }
}

// ---------------- launch ----------------
extern "C" void kernel_launch(void* const* d_in, const int* in_sizes, int n_in,
                              void* d_out, int out_size) {
    (void)in_sizes; (void)n_in; (void)out_size;
    const float* x  = (const float*)d_in[0];
    const float* wr = (const float*)d_in[1];
    const float* wi = (const float*)d_in[2];
    float* out = (float*)d_out;

    cudaFuncSetAttribute(kA_fwd, cudaFuncAttributeMaxDynamicSharedMemorySize, SMEM_BYTES);
    cudaFuncSetAttribute(kB_inv, cudaFuncAttributeMaxDynamicSharedMemorySize, SMEM_BYTES);

    kA_fwd <<<1536, 256, SMEM_BYTES>>>(x);    // 256 bc * 6 w-groups
    k3_wdft<<<256,  128>>>();                 // 32768 rows
    k4_mix <<<256,  256>>>(wr, wi);           // 2048 modes / 8 per block
    kB_inv <<<1536, 256, SMEM_BYTES>>>(out);  // 256 bd * 6 w-groups
}

// round 14
// speedup vs baseline: 1.5878x; 1.0071x over previous
#include <cuda_runtime.h>

// Problem constants
#define BB 8
#define CC 32
#define DD 32
#define TT 32
#define HH 96
#define WW 96
#define MT 8
#define MS 16
#define BC (BB*CC)        // 256
#define BD (BB*DD)        // 256
#define HW (HH*WW)        // 9216
#define NMODE (MT*MS*MS)  // 2048
#define NROW (BC*MT*MS)   // 32768 rows of F2
#define TWO_PI 6.28318530717958647692f

// Y/Z smem row stride (floats). 144: conflict-light in all phases.
#define ZSTR 144
#define SMEM_BYTES (2*HH*ZSTR*4)

// ---------------- scratch (static device globals; no allocation) ----------------
__device__ float g_F2r[WW*NROW];         // after T+H DFT, W-MAJOR: (w, bc*128+kt*16+kx)
__device__ float g_F2i[WW*NROW];
__device__ float g_F3r[BC*NMODE];        // after W-DFT: (bc, m)  m = kt*256+kx*16+ky
__device__ float g_F3i[BC*NMODE];
__device__ float g_Sr [2*BD*NMODE];      // after mix: TWO c-half partials (half, bd, m)
__device__ float g_Si [2*BD*NMODE];

// ---------------- compile-time trig (Taylor, double precision) ----------------
__host__ __device__ constexpr double ct_cos(double x) {
    double x2 = x * x, t = 1.0, s = 1.0;
    for (int k = 1; k <= 26; k++) { t *= -x2 / ((2.0*k - 1.0) * (2.0*k)); s += t; }
    return s;
}
__host__ __device__ constexpr double ct_sin(double x) {
    double x2 = x * x, t = x, s = x;
    for (int k = 1; k <= 26; k++) { t *= -x2 / ((2.0*k) * (2.0*k + 1.0)); s += t; }
    return s;
}

// Twiddle cos/sin(2*pi*P/N) with exact 0 / +-1 at quadrant points
template<int P, int N> struct TW {
    static constexpr int    q0 = ((P % N) + N) % N;
    static constexpr int    aq = (q0 > N - q0) ? (N - q0) : q0;
    static constexpr int    ss = (q0 > N/2) ? -1 : 1;
    static constexpr bool c_zero = (4*aq == N);
    static constexpr bool s_zero = (aq == 0) || (2*aq == N);
    static constexpr float c =
        (aq == 0)     ? 1.0f  :
        (2*aq == N)   ? -1.0f :
        c_zero        ? 0.0f  :
        (float)ct_cos(6.283185307179586476925286766559 * (double)aq / (double)N);
    static constexpr float s =
        s_zero        ? 0.0f :
        (4*aq == N)   ? (ss > 0 ? 1.0f : -1.0f) :
        (float)(ss * ct_sin(6.283185307179586476925286766559 * (double)aq / (double)N));
};

template<int P, int N, int SG = 1>
__device__ __forceinline__ float fC(float v, float acc) {
    using T = TW<P, N>;
    constexpr float cc = (SG < 0) ? -T::c : T::c;
    if constexpr (T::c_zero)         return acc;
    else if constexpr (cc ==  1.0f)  return acc + v;
    else if constexpr (cc == -1.0f)  return acc - v;
    else                             return fmaf(v, cc, acc);
}
template<int P, int N, int SG = 1>
__device__ __forceinline__ float fS(float v, float acc) {
    using T = TW<P, N>;
    constexpr float sv = (SG < 0) ? -T::s : T::s;
    if constexpr (T::s_zero)         return acc;
    else if constexpr (sv ==  1.0f)  return acc + v;
    else if constexpr (sv == -1.0f)  return acc - v;
    else                             return fmaf(v, sv, acc);
}
// float2 / float4 lane-wise versions
template<int P, int N, int SG = 1>
__device__ __forceinline__ void fC2(const float2 v, float2& a) {
    a.x = fC<P,N,SG>(v.x, a.x); a.y = fC<P,N,SG>(v.y, a.y);
}
template<int P, int N, int SG = 1>
__device__ __forceinline__ void fS2(const float2 v, float2& a) {
    a.x = fS<P,N,SG>(v.x, a.x); a.y = fS<P,N,SG>(v.y, a.y);
}
template<int P, int N, int SG = 1>
__device__ __forceinline__ void fC4(const float4 v, float4& a) {
    a.x = fC<P,N,SG>(v.x, a.x); a.y = fC<P,N,SG>(v.y, a.y);
    a.z = fC<P,N,SG>(v.z, a.z); a.w = fC<P,N,SG>(v.w, a.w);
}
template<int P, int N, int SG = 1>
__device__ __forceinline__ void fS4(const float4 v, float4& a) {
    a.x = fS<P,N,SG>(v.x, a.x); a.y = fS<P,N,SG>(v.y, a.y);
    a.z = fS<P,N,SG>(v.z, a.z); a.w = fS<P,N,SG>(v.w, a.w);
}
__device__ __forceinline__ float4 f4add(const float4 a, const float4 b) {
    return make_float4(a.x+b.x, a.y+b.y, a.z+b.z, a.w+b.w);
}
__device__ __forceinline__ float4 f4sub(const float4 a, const float4 b) {
    return make_float4(a.x-b.x, a.y-b.y, a.z-b.z, a.w-b.w);
}

// ---------------- compile-time unroller ----------------
template<int I> struct Ic { static constexpr int v = I; };
template<int I, int E, class F> __device__ __forceinline__ void UNR(F&& f) {
    if constexpr (I < E) { f(Ic<I>{}); UNR<I+1, E>(f); }
}

// ---------------- KA: fused T-DFT + H-DFT  (x -> F2, w-major) ----------------
__global__ void __maxnreg__(112) kA_fwd(const float* __restrict__ x) {
    extern __shared__ float sm[];
    float* Yr = sm;                     // HH*ZSTR floats
    float* Yi = sm + HH*ZSTR;
    const int tid = threadIdx.x;
    const int bc = blockIdx.x / 6;
    const int w0 = (blockIdx.x % 6) * 16;
    const float* xb = x + (size_t)bc * TT * HW + w0;

    // phase1: T-DFT (real -> complex), float2 lanes (2 w per thread), quad-streamed.
    {
        const int wl2 = tid & 7;
        const int hs  = tid >> 3;           // 0..31
        for (int p = 0; p < 3; p++) {
            const int h = p * 32 + hs;
            const float* xp = xb + h * WW + wl2 * 2;
            float2 ar[MT], ai[MT];
            {   // t = 0/16 and 8/24 specials
                float2 x0  = *reinterpret_cast<const float2*>(xp);
                float2 x8  = *reinterpret_cast<const float2*>(xp + (size_t)8  * HW);
                float2 x16 = *reinterpret_cast<const float2*>(xp + (size_t)16 * HW);
                float2 x24 = *reinterpret_cast<const float2*>(xp + (size_t)24 * HW);
                float2 xe0 = make_float2(x0.x + x16.x, x0.y + x16.y);
                float2 xo0 = make_float2(x0.x - x16.x, x0.y - x16.y);
                float2 xe8 = make_float2(x8.x + x24.x, x8.y + x24.y);
                float2 xo8 = make_float2(x8.x - x24.x, x8.y - x24.y);
                UNR<0,MT>([&](auto K){ constexpr int k = decltype(K)::v;
                    if constexpr ((k & 1) == 0) {
                        float2 t = xe0; fC2<k*8, TT>(xe8, t);
                        ar[k] = t; ai[k] = make_float2(0.f, 0.f);
                    } else {
                        ar[k] = xo0;
                        float2 t = make_float2(0.f, 0.f); fS2<k*8, TT, -1>(xo8, t);
                        ai[k] = t;
                    }
                });
            }
            UNR<1,8>([&](auto T){ constexpr int t = decltype(T)::v;
                float2 a = *reinterpret_cast<const float2*>(xp + (size_t)t        * HW);
                float2 b = *reinterpret_cast<const float2*>(xp + (size_t)(32 - t) * HW);
                float2 c = *reinterpret_cast<const float2*>(xp + (size_t)(16 - t) * HW);
                float2 d = *reinterpret_cast<const float2*>(xp + (size_t)(16 + t) * HW);
                float2 et = make_float2(a.x + d.x, a.y + d.y);   // xe[t]
                float2 ot = make_float2(a.x - d.x, a.y - d.y);   // xo[t]
                float2 em = make_float2(c.x + b.x, c.y + b.y);   // xe[16-t]
                float2 om = make_float2(c.x - b.x, c.y - b.y);   // xo[16-t]
                float2 pe = make_float2(et.x + em.x, et.y + em.y);
                float2 me = make_float2(et.x - em.x, et.y - em.y);
                float2 po = make_float2(ot.x + om.x, ot.y + om.y);
                float2 mo = make_float2(ot.x - om.x, ot.y - om.y);
                UNR<0,MT>([&](auto K){ constexpr int k = decltype(K)::v;
                    if constexpr ((k & 1) == 0) {
                        fC2<k*t, TT>(pe, ar[k]);
                        fS2<k*t, TT, -1>(me, ai[k]);
                    } else {
                        fC2<k*t, TT>(mo, ar[k]);
                        fS2<k*t, TT, -1>(po, ai[k]);
                    }
                });
            });
            UNR<0,MT>([&](auto K){ constexpr int k = decltype(K)::v;
                *reinterpret_cast<float2*>(Yr + h*ZSTR + k*16 + wl2*2) = ar[k];
                *reinterpret_cast<float2*>(Yi + h*ZSTR + k*16 + wl2*2) = ai[k]; });
        }
    }
    __syncthreads();

    // phase2: H-DFT. Even/odd kx banks + 48-domain mirror (R13). kx split in halves.
    {
        const int wl   = tid & 15;
        const int kt   = (tid >> 4) & 7;
        const int half = tid >> 7;
        const float* yr = Yr + kt*16 + wl;
        const float* yi = Yi + kt*16 + wl;
        auto run = [&](auto K0C){
            constexpr int K0 = decltype(K0C)::v;
            float fr[8], fi[8];
            {   // self-paired points: rows {0,48} and {24,72}
                float y0r = yr[0],        y0i = yi[0];
                float y48r = yr[48*ZSTR], y48i = yi[48*ZSTR];
                float y24r = yr[24*ZSTR], y24i = yi[24*ZSTR];
                float y72r = yr[72*ZSTR], y72i = yi[72*ZSTR];
                float u0r = y0r + y48r,  u0i = y0i + y48i;
                float v0r = y0r - y48r,  v0i = y0i - y48i;
                float u24r = y24r + y72r, u24i = y24i + y72i;
                float v24r = y24r - y72r, v24i = y24i - y72i;
                UNR<0,8>([&](auto J){ constexpr int j = decltype(J)::v; constexpr int kx = K0 + j;
                    if constexpr ((kx & 1) == 0) {
                        fr[j] = fC<kx*24, HH>(u24r, u0r);
                        fi[j] = fC<kx*24, HH>(u24i, u0i);
                    } else {
                        fr[j] = fS<kx*24, HH>(v24i, v0r);
                        fi[j] = fS<kx*24, HH, -1>(v24r, v0i);
                    }
                });
            }
            UNR<1,24>([&](auto H){ constexpr int h = decltype(H)::v;
                float yar = yr[h*ZSTR],      yai = yi[h*ZSTR];
                float ybr = yr[(96-h)*ZSTR], ybi = yi[(96-h)*ZSTR];
                float ycr = yr[(48+h)*ZSTR], yci = yi[(48+h)*ZSTR];
                float ydr = yr[(48-h)*ZSTR], ydi = yi[(48-h)*ZSTR];
                float uar = yar + ycr, uai = yai + yci;
                float ubr = ydr + ybr, ubi = ydi + ybi;
                float pa = uar + ubr, ma = uar - ubr;
                float pb = uai + ubi, mb = uai - ubi;
                float var_ = yar - ycr, vai = yai - yci;
                float vbr  = ydr - ybr, vbi = ydi - ybi;
                float qa = var_ - vbr, qm = var_ + vbr;
                float qb = vai - vbi,  qp = vai + vbi;
                UNR<0,8>([&](auto J){ constexpr int j = decltype(J)::v; constexpr int kx = K0 + j;
                    if constexpr ((kx & 1) == 0) {
                        fr[j] = fC<kx*h, HH>(pa, fS<kx*h, HH>(mb, fr[j]));
                        fi[j] = fC<kx*h, HH>(pb, fS<kx*h, HH, -1>(ma, fi[j]));
                    } else {
                        fr[j] = fC<kx*h, HH>(qa, fS<kx*h, HH>(qp, fr[j]));
                        fi[j] = fC<kx*h, HH>(qb, fS<kx*h, HH, -1>(qm, fi[j]));
                    }
                });
            });
            size_t base = (size_t)(w0 + wl) * NROW + bc*128 + kt*16 + K0;
            *reinterpret_cast<float4*>(g_F2r + base)     = make_float4(fr[0], fr[1], fr[2], fr[3]);
            *reinterpret_cast<float4*>(g_F2r + base + 4) = make_float4(fr[4], fr[5], fr[6], fr[7]);
            *reinterpret_cast<float4*>(g_F2i + base)     = make_float4(fi[0], fi[1], fi[2], fi[3]);
            *reinterpret_cast<float4*>(g_F2i + base + 4) = make_float4(fi[4], fi[5], fi[6], fi[7]);
        };
        if (half == 0) run(Ic<0>{}); else run(Ic<8>{});
    }
}

// ---------------- K3: W-DFT (F2 -> F3), coalesced, folded over w <-> 96-w ----------------
__global__ void __launch_bounds__(128) k3_wdft() {
    int r = blockIdx.x * 128 + threadIdx.x;       // 32768 rows, exact
    const float* pr = g_F2r + r;
    const float* pi = g_F2i + r;
    float fr[MS], fi[MS];
    {
        float a0  = pr[0],                  b0  = pi[0];
        float a48 = pr[(size_t)48 * NROW],  b48 = pi[(size_t)48 * NROW];
        UNR<0,MS>([&](auto K){ constexpr int ky = decltype(K)::v;
            fr[ky] = (ky & 1) ? (a0 - a48) : (a0 + a48);
            fi[ky] = (ky & 1) ? (b0 - b48) : (b0 + b48); });
    }
    UNR<1,48>([&](auto WI){ constexpr int w = decltype(WI)::v;
        float a  = pr[(size_t)w * NROW],      b  = pi[(size_t)w * NROW];
        float a2 = pr[(size_t)(96-w) * NROW], b2 = pi[(size_t)(96-w) * NROW];
        float pa = a + a2, ma = a - a2, pb = b + b2, mb = b - b2;
        UNR<0,MS>([&](auto K){ constexpr int ky = decltype(K)::v;
            fr[ky] = fC<w*ky, WW>(pa, fS<w*ky, WW>(mb, fr[ky]));
            fi[ky] = fC<w*ky, WW>(pb, fS<w*ky, WW, -1>(ma, fi[ky]));
        });
    });
    size_t o = (size_t)r * MS;
    UNR<0,MS>([&](auto K){ constexpr int ky = decltype(K)::v;
        g_F3r[o + ky] = fr[ky];
        g_F3i[o + ky] = fi[ky]; });
}

// ---------------- K4: channel mix, c-SPLIT (2 halves), weights ORIGINAL layout ----------------
// block = (8 modes, c-half). Each block sums 16 input channels into its partial-S buffer.
__global__ void __launch_bounds__(256) k4_mix(const float* __restrict__ wr,
                                              const float* __restrict__ wi) {
    __shared__ float Xr[BB*16*8], Xi[BB*16*8];   // 8 KB (b, c-local, m-local)
    const int m0 = (blockIdx.x >> 1) * 8;
    const int ch = blockIdx.x & 1;
    const int tid = threadIdx.x;
    for (int i = tid; i < BB*16*8; i += 256) {
        int bcl = i >> 3;                 // b*16 + cl
        int b = bcl >> 4, cl = bcl & 15, mm = i & 7;
        size_t src = (size_t)(b*CC + ch*16 + cl) * NMODE + m0 + mm;
        Xr[i] = g_F3r[src];
        Xi[i] = g_F3i[src];
    }
    __syncthreads();
    const int d  = tid >> 3;
    const int ml = tid & 7;
    const int m  = m0 + ml;
    const float* wrp = wr + ((size_t)(ch*16) * DD + d) * NMODE + m;
    const float* wip = wi + ((size_t)(ch*16) * DD + d) * NMODE + m;

    float sr[BB], si[BB];
#pragma unroll
    for (int b = 0; b < BB; b++) { sr[b] = 0.0f; si[b] = 0.0f; }

#pragma unroll
    for (int cl = 0; cl < 16; cl++) {
        float a  = wrp[(size_t)cl * DD * NMODE];
        float bb = wip[(size_t)cl * DD * NMODE];
#pragma unroll
        for (int b = 0; b < BB; b++) {
            float xr = Xr[(b*16 + cl)*8 + ml];
            float xi = Xi[(b*16 + cl)*8 + ml];
            sr[b] = fmaf(xr, a,  fmaf(-xi, bb, sr[b]));
            si[b] = fmaf(xr, bb, fmaf( xi, a,  si[b]));
        }
    }
    float sc = (((m & (MS-1)) == 0) ? 1.0f : 2.0f) * (1.0f / 294912.0f);
#pragma unroll
    for (int b = 0; b < BB; b++) {
        size_t o = (size_t)ch * BD * NMODE + (size_t)(b*DD + d) * NMODE + m;
        g_Sr[o] = sr[b] * sc;
        g_Si[o] = si[b] * sc;
    }
}

// ---------------- KB: fused W-exp + H-exp + T-exp  (S -> out) ----------------
__global__ void __maxnreg__(112) kB_inv(float* __restrict__ out) {
    extern __shared__ float sm[];
    float* Zr  = sm;                             // HH*ZSTR floats
    float* Zi  = sm + HH*ZSTR;
    float*  Ssr = sm;                            // phase0 staging aliases Z
    float*  Ssi = sm + 2048;
    float2* tab = reinterpret_cast<float2*>(sm + 4096);   // [ky][wl] 256 float2

    const int tid = threadIdx.x;
    const int bd = blockIdx.x / 6;
    const int w0 = (blockIdx.x % 6) * 16;
    const int wl = tid & 15;
    const int kt = (tid >> 4) & 7;
    const int half = tid >> 7;

    {   // load S tile = sum of the two c-half partials (coalesced, float4)
        const float4* s0r = reinterpret_cast<const float4*>(g_Sr + (size_t)bd * NMODE);
        const float4* s1r = reinterpret_cast<const float4*>(g_Sr + (size_t)BD * NMODE + (size_t)bd * NMODE);
        const float4* s0i = reinterpret_cast<const float4*>(g_Si + (size_t)bd * NMODE);
        const float4* s1i = reinterpret_cast<const float4*>(g_Si + (size_t)BD * NMODE + (size_t)bd * NMODE);
#pragma unroll
        for (int q = 0; q < 2; q++) {
            int i = tid + q*256;
            float4 a = s0r[i], b = s1r[i];
            reinterpret_cast<float4*>(Ssr)[i] = f4add(a, b);
            float4 c = s0i[i], d = s1i[i];
            reinterpret_cast<float4*>(Ssi)[i] = f4add(c, d);
        }
        {
            int ky = tid >> 4, wl2 = tid & 15;
            float ssin, ccos;
            sincosf(TWO_PI * (float)((ky * (w0 + wl2)) % WW) / (float)WW, &ssin, &ccos);
            tab[tid] = make_float2(ccos, ssin);
        }
    }
    __syncthreads();

    // phase0: W-expand into registers, all 16 kx per thread, e^{+i 2pi ky w / 96}.
    float a1r[MS], a1i[MS];
    {
        float ec[MS], es[MS];
#pragma unroll
        for (int ky = 0; ky < MS; ky++) { float2 e = tab[ky*16 + wl]; ec[ky] = e.x; es[ky] = e.y; }
#pragma unroll
        for (int kx = 0; kx < MS; kx++) {
            const float4* pr4 = reinterpret_cast<const float4*>(Ssr + (kt*MS + kx) * MS);
            const float4* pi4 = reinterpret_cast<const float4*>(Ssi + (kt*MS + kx) * MS);
            float rr = 0.f, ii = 0.f;
#pragma unroll
            for (int q = 0; q < 4; q++) {
                float4 vr = pr4[q];
                float4 vi = pi4[q];
                rr = fmaf(vr.x, ec[q*4+0], fmaf(-vi.x, es[q*4+0], rr));
                ii = fmaf(vr.x, es[q*4+0], fmaf( vi.x, ec[q*4+0], ii));
                rr = fmaf(vr.y, ec[q*4+1], fmaf(-vi.y, es[q*4+1], rr));
                ii = fmaf(vr.y, es[q*4+1], fmaf( vi.y, ec[q*4+1], ii));
                rr = fmaf(vr.z, ec[q*4+2], fmaf(-vi.z, es[q*4+2], rr));
                ii = fmaf(vr.z, es[q*4+2], fmaf( vi.z, ec[q*4+2], ii));
                rr = fmaf(vr.w, ec[q*4+3], fmaf(-vi.w, es[q*4+3], rr));
                ii = fmaf(vr.w, es[q*4+3], fmaf( vi.w, ec[q*4+3], ii));
            }
            a1r[kx] = rr; a1i[kx] = ii;
        }
    }
    __syncthreads();   // staging reads done before Z overwrites

    // phase1: H-expand with quad fold {h, 96-h, 48+h, 48-h} via even/odd kx chains.
    {
        auto quad = [&](auto H){ constexpr int h = decltype(H)::v;
            float Ce=0.f, Co=0.f, Se=0.f, So=0.f, C2e=0.f, C2o=0.f, S2e=0.f, S2o=0.f;
            UNR<0,8>([&](auto E){ constexpr int kx = 2 * decltype(E)::v;
                Ce  = fC<kx*h, HH>(a1r[kx], Ce);
                C2e = fC<kx*h, HH>(a1i[kx], C2e);
                Se  = fS<kx*h, HH>(a1i[kx], Se);
                S2e = fS<kx*h, HH>(a1r[kx], S2e);
            });
            UNR<0,8>([&](auto O){ constexpr int kx = 2 * decltype(O)::v + 1;
                Co  = fC<kx*h, HH>(a1r[kx], Co);
                C2o = fC<kx*h, HH>(a1i[kx], C2o);
                So  = fS<kx*h, HH>(a1i[kx], So);
                S2o = fS<kx*h, HH>(a1r[kx], S2o);
            });
            float Cp = Ce+Co, Cm = Ce-Co, Sp = Se+So, Sm = Se-So;
            float C2p = C2e+C2o, C2m = C2e-C2o, S2p = S2e+S2o, S2m = S2e-S2o;
            Zr[h*ZSTR + kt*16 + wl]      = Cp - Sp;
            Zi[h*ZSTR + kt*16 + wl]      = C2p + S2p;
            Zr[(96-h)*ZSTR + kt*16 + wl] = Cp + Sp;
            Zi[(96-h)*ZSTR + kt*16 + wl] = C2p - S2p;
            Zr[(48+h)*ZSTR + kt*16 + wl] = Cm - Sm;
            Zi[(48+h)*ZSTR + kt*16 + wl] = C2m + S2m;
            Zr[(48-h)*ZSTR + kt*16 + wl] = Cm + Sm;
            Zi[(48-h)*ZSTR + kt*16 + wl] = C2m - S2m;
        };
        if (half == 0) {
            {   // self points {0, 48}
                float s0r=0.f, s0i=0.f, s48r=0.f, s48i=0.f;
                UNR<0,MS>([&](auto K){ constexpr int kx = decltype(K)::v;
                    s0r += a1r[kx]; s0i += a1i[kx];
                    if constexpr (kx & 1) { s48r -= a1r[kx]; s48i -= a1i[kx]; }
                    else                  { s48r += a1r[kx]; s48i += a1i[kx]; } });
                Zr[0*ZSTR + kt*16 + wl]  = s0r;  Zi[0*ZSTR + kt*16 + wl]  = s0i;
                Zr[48*ZSTR + kt*16 + wl] = s48r; Zi[48*ZSTR + kt*16 + wl] = s48i;
            }
            UNR<1,13>(quad);
        } else {
            UNR<13,25>(quad);
        }
    }
    __syncthreads();

    // phase2: T-expand + real part, quad fold {t, 32-t, 16+t, 16-t}.
    // float4 lanes (4 w per thread); t-range split across thread halves.
    {
        const int wl4 = tid & 3;
        const int hs  = (tid >> 2) & 31;
        const int hf  = tid >> 7;
        float* ob = out + (size_t)bd * TT * HW + w0 + wl4*4;
        for (int p = 0; p < 3; p++) {
            const int h = p * 32 + hs;
            float4 zr[MT], zi[MT];
            UNR<0,MT>([&](auto K){ constexpr int k = decltype(K)::v;
                zr[k] = *reinterpret_cast<const float4*>(Zr + h*ZSTR + k*16 + wl4*4);
                zi[k] = *reinterpret_cast<const float4*>(Zi + h*ZSTR + k*16 + wl4*4); });
            float* op = ob + h * WW;
            auto quad = [&](auto T){ constexpr int t = decltype(T)::v;
                float4 Ce = make_float4(0,0,0,0), Co = make_float4(0,0,0,0);
                float4 Se = make_float4(0,0,0,0), So = make_float4(0,0,0,0);
                UNR<0,4>([&](auto E){ constexpr int k = 2 * decltype(E)::v;
                    fC4<k*t, TT>(zr[k], Ce);
                    fS4<k*t, TT>(zi[k], Se); });
                UNR<0,4>([&](auto O){ constexpr int k = 2 * decltype(O)::v + 1;
                    fC4<k*t, TT>(zr[k], Co);
                    fS4<k*t, TT>(zi[k], So); });
                float4 Cp = f4add(Ce, Co), Cm = f4sub(Ce, Co);
                float4 Sp = f4add(Se, So), Sm = f4sub(Se, So);
                *reinterpret_cast<float4*>(op + (size_t)t * HW)        = f4sub(Cp, Sp);
                *reinterpret_cast<float4*>(op + (size_t)(32 - t) * HW) = f4add(Cp, Sp);
                *reinterpret_cast<float4*>(op + (size_t)(16 + t) * HW) = f4sub(Cm, Sm);
                *reinterpret_cast<float4*>(op + (size_t)(16 - t) * HW) = f4add(Cm, Sm);
            };
            if (hf == 0) {
                {   // t = 0 and 16
                    float4 s0 = make_float4(0,0,0,0), s16 = make_float4(0,0,0,0);
                    UNR<0,MT>([&](auto K){ constexpr int k = decltype(K)::v;
                        s0 = f4add(s0, zr[k]);
                        if constexpr (k & 1) s16 = f4sub(s16, zr[k]);
                        else                 s16 = f4add(s16, zr[k]); });
                    *reinterpret_cast<float4*>(op)                   = s0;
                    *reinterpret_cast<float4*>(op + (size_t)16 * HW) = s16;
                }
                {   // t = 8 and 24
                    float4 Ce = make_float4(0,0,0,0), So = make_float4(0,0,0,0);
                    UNR<0,4>([&](auto E){ constexpr int k = 2 * decltype(E)::v;
                        fC4<k*8, TT>(zr[k], Ce); });
                    UNR<0,4>([&](auto O){ constexpr int k = 2 * decltype(O)::v + 1;
                        fS4<k*8, TT>(zi[k], So); });
                    *reinterpret_cast<float4*>(op + (size_t)8  * HW) = f4sub(Ce, So);
                    *reinterpret_cast<float4*>(op + (size_t)24 * HW) = f4add(Ce, So);
                }
                quad(Ic<1>{}); quad(Ic<2>{}); quad(Ic<3>{});
            } else {
                quad(Ic<4>{}); quad(Ic<5>{}); quad(Ic<6>{}); quad(Ic<7>{});
            }
        }
    }
}

// ---------------- launch ----------------
extern "C" void kernel_launch(void* const* d_in, const int* in_sizes, int n_in,
                              void* d_out, int out_size) {
    (void)in_sizes; (void)n_in; (void)out_size;
    const float* x  = (const float*)d_in[0];
    const float* wr = (const float*)d_in[1];
    const float* wi = (const float*)d_in[2];
    float* out = (float*)d_out;

    cudaFuncSetAttribute(kA_fwd, cudaFuncAttributeMaxDynamicSharedMemorySize, SMEM_BYTES);
    cudaFuncSetAttribute(kB_inv, cudaFuncAttributeMaxDynamicSharedMemorySize, SMEM_BYTES);

    kA_fwd <<<1536, 256, SMEM_BYTES>>>(x);    // 256 bc * 6 w-groups
    k3_wdft<<<256,  128>>>();                 // 32768 rows
    k4_mix <<<512,  256>>>(wr, wi);           // 256 mode-groups x 2 c-halves
    kB_inv <<<1536, 256, SMEM_BYTES>>>(out);  // 256 bd * 6 w-groups
}

// round 15
// speedup vs baseline: 1.6139x; 1.0165x over previous
#include <cuda_runtime.h>

// Problem constants
#define BB 8
#define CC 32
#define DD 32
#define TT 32
#define HH 96
#define WW 96
#define MT 8
#define MS 16
#define BC (BB*CC)        // 256
#define BD (BB*DD)        // 256
#define HW (HH*WW)        // 9216
#define NMODE (MT*MS*MS)  // 2048
#define NROW (BC*MT*MS)   // 32768 rows of F2
#define TWO_PI 6.28318530717958647692f

// Y/Z smem row stride (floats). 144: conflict-light in all phases.
#define ZSTR 144
#define SMEM_BYTES (2*HH*ZSTR*4)

// ---------------- scratch (static device globals; no allocation) ----------------
__device__ float g_F2r[WW*NROW];         // after T+H DFT, W-MAJOR: (w, bc*128+kt*16+kx)
__device__ float g_F2i[WW*NROW];
__device__ float g_F3r[BC*NMODE];        // after W-DFT: (bc, m)  m = kt*256+kx*16+ky
__device__ float g_F3i[BC*NMODE];
__device__ float g_Sr [2*BD*NMODE];      // after mix: TWO c-half partials (half, bd, m)
__device__ float g_Si [2*BD*NMODE];

// ---------------- compile-time trig (Taylor, double precision) ----------------
__host__ __device__ constexpr double ct_cos(double x) {
    double x2 = x * x, t = 1.0, s = 1.0;
    for (int k = 1; k <= 26; k++) { t *= -x2 / ((2.0*k - 1.0) * (2.0*k)); s += t; }
    return s;
}
__host__ __device__ constexpr double ct_sin(double x) {
    double x2 = x * x, t = x, s = x;
    for (int k = 1; k <= 26; k++) { t *= -x2 / ((2.0*k) * (2.0*k + 1.0)); s += t; }
    return s;
}

// Twiddle cos/sin(2*pi*P/N) with exact 0 / +-1 at quadrant points
template<int P, int N> struct TW {
    static constexpr int    q0 = ((P % N) + N) % N;
    static constexpr int    aq = (q0 > N - q0) ? (N - q0) : q0;
    static constexpr int    ss = (q0 > N/2) ? -1 : 1;
    static constexpr bool c_zero = (4*aq == N);
    static constexpr bool s_zero = (aq == 0) || (2*aq == N);
    static constexpr float c =
        (aq == 0)     ? 1.0f  :
        (2*aq == N)   ? -1.0f :
        c_zero        ? 0.0f  :
        (float)ct_cos(6.283185307179586476925286766559 * (double)aq / (double)N);
    static constexpr float s =
        s_zero        ? 0.0f :
        (4*aq == N)   ? (ss > 0 ? 1.0f : -1.0f) :
        (float)(ss * ct_sin(6.283185307179586476925286766559 * (double)aq / (double)N));
};

template<int P, int N, int SG = 1>
__device__ __forceinline__ float fC(float v, float acc) {
    using T = TW<P, N>;
    constexpr float cc = (SG < 0) ? -T::c : T::c;
    if constexpr (T::c_zero)         return acc;
    else if constexpr (cc ==  1.0f)  return acc + v;
    else if constexpr (cc == -1.0f)  return acc - v;
    else                             return fmaf(v, cc, acc);
}
template<int P, int N, int SG = 1>
__device__ __forceinline__ float fS(float v, float acc) {
    using T = TW<P, N>;
    constexpr float sv = (SG < 0) ? -T::s : T::s;
    if constexpr (T::s_zero)         return acc;
    else if constexpr (sv ==  1.0f)  return acc + v;
    else if constexpr (sv == -1.0f)  return acc - v;
    else                             return fmaf(v, sv, acc);
}
// float2 lane-wise versions
template<int P, int N, int SG = 1>
__device__ __forceinline__ void fC2(const float2 v, float2& a) {
    a.x = fC<P,N,SG>(v.x, a.x); a.y = fC<P,N,SG>(v.y, a.y);
}
template<int P, int N, int SG = 1>
__device__ __forceinline__ void fS2(const float2 v, float2& a) {
    a.x = fS<P,N,SG>(v.x, a.x); a.y = fS<P,N,SG>(v.y, a.y);
}
__device__ __forceinline__ float4 f4add(const float4 a, const float4 b) {
    return make_float4(a.x+b.x, a.y+b.y, a.z+b.z, a.w+b.w);
}

// ---------------- compile-time unroller ----------------
template<int I> struct Ic { static constexpr int v = I; };
template<int I, int E, class F> __device__ __forceinline__ void UNR(F&& f) {
    if constexpr (I < E) { f(Ic<I>{}); UNR<I+1, E>(f); }
}

// ---------------- KA: fused T-DFT + H-DFT  (x -> F2, w-major) ----------------
__global__ void __maxnreg__(112) kA_fwd(const float* __restrict__ x) {
    extern __shared__ float sm[];
    float* Yr = sm;                     // HH*ZSTR floats
    float* Yi = sm + HH*ZSTR;
    const int tid = threadIdx.x;
    const int bc = blockIdx.x / 6;
    const int w0 = (blockIdx.x % 6) * 16;
    const float* xb = x + (size_t)bc * TT * HW + w0;

    // phase1: T-DFT (real -> complex), float2 lanes (2 w per thread), quad-streamed.
    {
        const int wl2 = tid & 7;
        const int hs  = tid >> 3;           // 0..31
        for (int p = 0; p < 3; p++) {
            const int h = p * 32 + hs;
            const float* xp = xb + h * WW + wl2 * 2;
            float2 ar[MT], ai[MT];
            {   // t = 0/16 and 8/24 specials
                float2 x0  = *reinterpret_cast<const float2*>(xp);
                float2 x8  = *reinterpret_cast<const float2*>(xp + (size_t)8  * HW);
                float2 x16 = *reinterpret_cast<const float2*>(xp + (size_t)16 * HW);
                float2 x24 = *reinterpret_cast<const float2*>(xp + (size_t)24 * HW);
                float2 xe0 = make_float2(x0.x + x16.x, x0.y + x16.y);
                float2 xo0 = make_float2(x0.x - x16.x, x0.y - x16.y);
                float2 xe8 = make_float2(x8.x + x24.x, x8.y + x24.y);
                float2 xo8 = make_float2(x8.x - x24.x, x8.y - x24.y);
                UNR<0,MT>([&](auto K){ constexpr int k = decltype(K)::v;
                    if constexpr ((k & 1) == 0) {
                        float2 t = xe0; fC2<k*8, TT>(xe8, t);
                        ar[k] = t; ai[k] = make_float2(0.f, 0.f);
                    } else {
                        ar[k] = xo0;
                        float2 t = make_float2(0.f, 0.f); fS2<k*8, TT, -1>(xo8, t);
                        ai[k] = t;
                    }
                });
            }
            UNR<1,8>([&](auto T){ constexpr int t = decltype(T)::v;
                float2 a = *reinterpret_cast<const float2*>(xp + (size_t)t        * HW);
                float2 b = *reinterpret_cast<const float2*>(xp + (size_t)(32 - t) * HW);
                float2 c = *reinterpret_cast<const float2*>(xp + (size_t)(16 - t) * HW);
                float2 d = *reinterpret_cast<const float2*>(xp + (size_t)(16 + t) * HW);
                float2 et = make_float2(a.x + d.x, a.y + d.y);   // xe[t]
                float2 ot = make_float2(a.x - d.x, a.y - d.y);   // xo[t]
                float2 em = make_float2(c.x + b.x, c.y + b.y);   // xe[16-t]
                float2 om = make_float2(c.x - b.x, c.y - b.y);   // xo[16-t]
                float2 pe = make_float2(et.x + em.x, et.y + em.y);
                float2 me = make_float2(et.x - em.x, et.y - em.y);
                float2 po = make_float2(ot.x + om.x, ot.y + om.y);
                float2 mo = make_float2(ot.x - om.x, ot.y - om.y);
                UNR<0,MT>([&](auto K){ constexpr int k = decltype(K)::v;
                    if constexpr ((k & 1) == 0) {
                        fC2<k*t, TT>(pe, ar[k]);
                        fS2<k*t, TT, -1>(me, ai[k]);
                    } else {
                        fC2<k*t, TT>(mo, ar[k]);
                        fS2<k*t, TT, -1>(po, ai[k]);
                    }
                });
            });
            UNR<0,MT>([&](auto K){ constexpr int k = decltype(K)::v;
                *reinterpret_cast<float2*>(Yr + h*ZSTR + k*16 + wl2*2) = ar[k];
                *reinterpret_cast<float2*>(Yi + h*ZSTR + k*16 + wl2*2) = ai[k]; });
        }
    }
    __syncthreads();

    // phase2: H-DFT. Even/odd kx banks + 48-domain mirror. kx split in halves.
    {
        const int wl   = tid & 15;
        const int kt   = (tid >> 4) & 7;
        const int half = tid >> 7;
        const float* yr = Yr + kt*16 + wl;
        const float* yi = Yi + kt*16 + wl;
        auto run = [&](auto K0C){
            constexpr int K0 = decltype(K0C)::v;
            float fr[8], fi[8];
            {   // self-paired points: rows {0,48} and {24,72}
                float y0r = yr[0],        y0i = yi[0];
                float y48r = yr[48*ZSTR], y48i = yi[48*ZSTR];
                float y24r = yr[24*ZSTR], y24i = yi[24*ZSTR];
                float y72r = yr[72*ZSTR], y72i = yi[72*ZSTR];
                float u0r = y0r + y48r,  u0i = y0i + y48i;
                float v0r = y0r - y48r,  v0i = y0i - y48i;
                float u24r = y24r + y72r, u24i = y24i + y72i;
                float v24r = y24r - y72r, v24i = y24i - y72i;
                UNR<0,8>([&](auto J){ constexpr int j = decltype(J)::v; constexpr int kx = K0 + j;
                    if constexpr ((kx & 1) == 0) {
                        fr[j] = fC<kx*24, HH>(u24r, u0r);
                        fi[j] = fC<kx*24, HH>(u24i, u0i);
                    } else {
                        fr[j] = fS<kx*24, HH>(v24i, v0r);
                        fi[j] = fS<kx*24, HH, -1>(v24r, v0i);
                    }
                });
            }
            UNR<1,24>([&](auto H){ constexpr int h = decltype(H)::v;
                float yar = yr[h*ZSTR],      yai = yi[h*ZSTR];
                float ybr = yr[(96-h)*ZSTR], ybi = yi[(96-h)*ZSTR];
                float ycr = yr[(48+h)*ZSTR], yci = yi[(48+h)*ZSTR];
                float ydr = yr[(48-h)*ZSTR], ydi = yi[(48-h)*ZSTR];
                float uar = yar + ycr, uai = yai + yci;
                float ubr = ydr + ybr, ubi = ydi + ybi;
                float pa = uar + ubr, ma = uar - ubr;
                float pb = uai + ubi, mb = uai - ubi;
                float var_ = yar - ycr, vai = yai - yci;
                float vbr  = ydr - ybr, vbi = ydi - ybi;
                float qa = var_ - vbr, qm = var_ + vbr;
                float qb = vai - vbi,  qp = vai + vbi;
                UNR<0,8>([&](auto J){ constexpr int j = decltype(J)::v; constexpr int kx = K0 + j;
                    if constexpr ((kx & 1) == 0) {
                        fr[j] = fC<kx*h, HH>(pa, fS<kx*h, HH>(mb, fr[j]));
                        fi[j] = fC<kx*h, HH>(pb, fS<kx*h, HH, -1>(ma, fi[j]));
                    } else {
                        fr[j] = fC<kx*h, HH>(qa, fS<kx*h, HH>(qp, fr[j]));
                        fi[j] = fC<kx*h, HH>(qb, fS<kx*h, HH, -1>(qm, fi[j]));
                    }
                });
            });
            size_t base = (size_t)(w0 + wl) * NROW + bc*128 + kt*16 + K0;
            *reinterpret_cast<float4*>(g_F2r + base)     = make_float4(fr[0], fr[1], fr[2], fr[3]);
            *reinterpret_cast<float4*>(g_F2r + base + 4) = make_float4(fr[4], fr[5], fr[6], fr[7]);
            *reinterpret_cast<float4*>(g_F2i + base)     = make_float4(fi[0], fi[1], fi[2], fi[3]);
            *reinterpret_cast<float4*>(g_F2i + base + 4) = make_float4(fi[4], fi[5], fi[6], fi[7]);
        };
        if (half == 0) run(Ic<0>{}); else run(Ic<8>{});
    }
}

// ---------------- K3: W-DFT (F2 -> F3), coalesced, folded over w <-> 96-w ----------------
__global__ void __launch_bounds__(128) k3_wdft() {
    int r = blockIdx.x * 128 + threadIdx.x;       // 32768 rows, exact
    const float* pr = g_F2r + r;
    const float* pi = g_F2i + r;
    float fr[MS], fi[MS];
    {
        float a0  = pr[0],                  b0  = pi[0];
        float a48 = pr[(size_t)48 * NROW],  b48 = pi[(size_t)48 * NROW];
        UNR<0,MS>([&](auto K){ constexpr int ky = decltype(K)::v;
            fr[ky] = (ky & 1) ? (a0 - a48) : (a0 + a48);
            fi[ky] = (ky & 1) ? (b0 - b48) : (b0 + b48); });
    }
    UNR<1,48>([&](auto WI){ constexpr int w = decltype(WI)::v;
        float a  = pr[(size_t)w * NROW],      b  = pi[(size_t)w * NROW];
        float a2 = pr[(size_t)(96-w) * NROW], b2 = pi[(size_t)(96-w) * NROW];
        float pa = a + a2, ma = a - a2, pb = b + b2, mb = b - b2;
        UNR<0,MS>([&](auto K){ constexpr int ky = decltype(K)::v;
            fr[ky] = fC<w*ky, WW>(pa, fS<w*ky, WW>(mb, fr[ky]));
            fi[ky] = fC<w*ky, WW>(pb, fS<w*ky, WW, -1>(ma, fi[ky]));
        });
    });
    size_t o = (size_t)r * MS;
    UNR<0,MS>([&](auto K){ constexpr int ky = decltype(K)::v;
        g_F3r[o + ky] = fr[ky];
        g_F3i[o + ky] = fi[ky]; });
}

// ---------------- K4: channel mix, c-SPLIT (2 halves), weights ORIGINAL layout ----------------
__global__ void __launch_bounds__(256) k4_mix(const float* __restrict__ wr,
                                              const float* __restrict__ wi) {
    __shared__ float Xr[BB*16*8], Xi[BB*16*8];   // 8 KB (b, c-local, m-local)
    const int m0 = (blockIdx.x >> 1) * 8;
    const int ch = blockIdx.x & 1;
    const int tid = threadIdx.x;
    for (int i = tid; i < BB*16*8; i += 256) {
        int bcl = i >> 3;                 // b*16 + cl
        int b = bcl >> 4, cl = bcl & 15, mm = i & 7;
        size_t src = (size_t)(b*CC + ch*16 + cl) * NMODE + m0 + mm;
        Xr[i] = g_F3r[src];
        Xi[i] = g_F3i[src];
    }
    __syncthreads();
    const int d  = tid >> 3;
    const int ml = tid & 7;
    const int m  = m0 + ml;
    const float* wrp = wr + ((size_t)(ch*16) * DD + d) * NMODE + m;
    const float* wip = wi + ((size_t)(ch*16) * DD + d) * NMODE + m;

    float sr[BB], si[BB];
#pragma unroll
    for (int b = 0; b < BB; b++) { sr[b] = 0.0f; si[b] = 0.0f; }

#pragma unroll
    for (int cl = 0; cl < 16; cl++) {
        float a  = wrp[(size_t)cl * DD * NMODE];
        float bb = wip[(size_t)cl * DD * NMODE];
#pragma unroll
        for (int b = 0; b < BB; b++) {
            float xr = Xr[(b*16 + cl)*8 + ml];
            float xi = Xi[(b*16 + cl)*8 + ml];
            sr[b] = fmaf(xr, a,  fmaf(-xi, bb, sr[b]));
            si[b] = fmaf(xr, bb, fmaf( xi, a,  si[b]));
        }
    }
    float sc = (((m & (MS-1)) == 0) ? 1.0f : 2.0f) * (1.0f / 294912.0f);
#pragma unroll
    for (int b = 0; b < BB; b++) {
        size_t o = (size_t)ch * BD * NMODE + (size_t)(b*DD + d) * NMODE + m;
        g_Sr[o] = sr[b] * sc;
        g_Si[o] = si[b] * sc;
    }
}

// ---------------- KB: fused W-exp + H-exp + T-exp  (S -> out), R13 structure ----------------
__global__ void __maxnreg__(112) kB_inv(float* __restrict__ out) {
    extern __shared__ float sm[];
    float* Zr  = sm;                             // HH*ZSTR floats
    float* Zi  = sm + HH*ZSTR;
    float*  Ssr = sm;                            // phase0 staging aliases Z
    float*  Ssi = sm + 2048;
    float2* tab = reinterpret_cast<float2*>(sm + 4096);   // [ky][wl] 256 float2

    const int tid = threadIdx.x;
    const int bd = blockIdx.x / 6;
    const int w0 = (blockIdx.x % 6) * 16;
    const int wl = tid & 15;
    const int kt = (tid >> 4) & 7;
    const int half = tid >> 7;

    {   // load S tile = sum of the two c-half partials (coalesced, float4)
        const float4* s0r = reinterpret_cast<const float4*>(g_Sr + (size_t)bd * NMODE);
        const float4* s1r = reinterpret_cast<const float4*>(g_Sr + (size_t)BD * NMODE + (size_t)bd * NMODE);
        const float4* s0i = reinterpret_cast<const float4*>(g_Si + (size_t)bd * NMODE);
        const float4* s1i = reinterpret_cast<const float4*>(g_Si + (size_t)BD * NMODE + (size_t)bd * NMODE);
#pragma unroll
        for (int q = 0; q < 2; q++) {
            int i = tid + q*256;
            reinterpret_cast<float4*>(Ssr)[i] = f4add(s0r[i], s1r[i]);
            reinterpret_cast<float4*>(Ssi)[i] = f4add(s0i[i], s1i[i]);
        }
        {
            int ky = tid >> 4, wl2 = tid & 15;
            float ssin, ccos;
            sincosf(TWO_PI * (float)((ky * (w0 + wl2)) % WW) / (float)WW, &ssin, &ccos);
            tab[tid] = make_float2(ccos, ssin);
        }
    }
    __syncthreads();

    // phase0: W-expand into registers, all 16 kx per thread, e^{+i 2pi ky w / 96}.
    float a1r[MS], a1i[MS];
    {
        float ec[MS], es[MS];
#pragma unroll
        for (int ky = 0; ky < MS; ky++) { float2 e = tab[ky*16 + wl]; ec[ky] = e.x; es[ky] = e.y; }
#pragma unroll
        for (int kx = 0; kx < MS; kx++) {
            const float4* pr4 = reinterpret_cast<const float4*>(Ssr + (kt*MS + kx) * MS);
            const float4* pi4 = reinterpret_cast<const float4*>(Ssi + (kt*MS + kx) * MS);
            float rr = 0.f, ii = 0.f;
#pragma unroll
            for (int q = 0; q < 4; q++) {
                float4 vr = pr4[q];
                float4 vi = pi4[q];
                rr = fmaf(vr.x, ec[q*4+0], fmaf(-vi.x, es[q*4+0], rr));
                ii = fmaf(vr.x, es[q*4+0], fmaf( vi.x, ec[q*4+0], ii));
                rr = fmaf(vr.y, ec[q*4+1], fmaf(-vi.y, es[q*4+1], rr));
                ii = fmaf(vr.y, es[q*4+1], fmaf( vi.y, ec[q*4+1], ii));
                rr = fmaf(vr.z, ec[q*4+2], fmaf(-vi.z, es[q*4+2], rr));
                ii = fmaf(vr.z, es[q*4+2], fmaf( vi.z, ec[q*4+2], ii));
                rr = fmaf(vr.w, ec[q*4+3], fmaf(-vi.w, es[q*4+3], rr));
                ii = fmaf(vr.w, es[q*4+3], fmaf( vi.w, ec[q*4+3], ii));
            }
            a1r[kx] = rr; a1i[kx] = ii;
        }
    }
    __syncthreads();   // staging reads done before Z overwrites

    // phase1: H-expand with quad fold {h, 96-h, 48+h, 48-h} via even/odd kx chains.
    {
        auto quad = [&](auto H){ constexpr int h = decltype(H)::v;
            float Ce=0.f, Co=0.f, Se=0.f, So=0.f, C2e=0.f, C2o=0.f, S2e=0.f, S2o=0.f;
            UNR<0,8>([&](auto E){ constexpr int kx = 2 * decltype(E)::v;
                Ce  = fC<kx*h, HH>(a1r[kx], Ce);
                C2e = fC<kx*h, HH>(a1i[kx], C2e);
                Se  = fS<kx*h, HH>(a1i[kx], Se);
                S2e = fS<kx*h, HH>(a1r[kx], S2e);
            });
            UNR<0,8>([&](auto O){ constexpr int kx = 2 * decltype(O)::v + 1;
                Co  = fC<kx*h, HH>(a1r[kx], Co);
                C2o = fC<kx*h, HH>(a1i[kx], C2o);
                So  = fS<kx*h, HH>(a1i[kx], So);
                S2o = fS<kx*h, HH>(a1r[kx], S2o);
            });
            float Cp = Ce+Co, Cm = Ce-Co, Sp = Se+So, Sm = Se-So;
            float C2p = C2e+C2o, C2m = C2e-C2o, S2p = S2e+S2o, S2m = S2e-S2o;
            Zr[h*ZSTR + kt*16 + wl]      = Cp - Sp;
            Zi[h*ZSTR + kt*16 + wl]      = C2p + S2p;
            Zr[(96-h)*ZSTR + kt*16 + wl] = Cp + Sp;
            Zi[(96-h)*ZSTR + kt*16 + wl] = C2p - S2p;
            Zr[(48+h)*ZSTR + kt*16 + wl] = Cm - Sm;
            Zi[(48+h)*ZSTR + kt*16 + wl] = C2m + S2m;
            Zr[(48-h)*ZSTR + kt*16 + wl] = Cm + Sm;
            Zi[(48-h)*ZSTR + kt*16 + wl] = C2m - S2m;
        };
        if (half == 0) {
            {   // self points {0, 48}
                float s0r=0.f, s0i=0.f, s48r=0.f, s48i=0.f;
                UNR<0,MS>([&](auto K){ constexpr int kx = decltype(K)::v;
                    s0r += a1r[kx]; s0i += a1i[kx];
                    if constexpr (kx & 1) { s48r -= a1r[kx]; s48i -= a1i[kx]; }
                    else                  { s48r += a1r[kx]; s48i += a1i[kx]; } });
                Zr[0*ZSTR + kt*16 + wl]  = s0r;  Zi[0*ZSTR + kt*16 + wl]  = s0i;
                Zr[48*ZSTR + kt*16 + wl] = s48r; Zi[48*ZSTR + kt*16 + wl] = s48i;
            }
            UNR<1,13>(quad);
        } else {
            UNR<13,25>(quad);
        }
    }
    __syncthreads();

    // phase2: T-expand + real part, quad fold {t, 32-t, 16+t, 16-t}; float2 lanes.
    {
        const int wl2 = tid & 7;
        const int hs  = tid >> 3;           // 0..31
        float* ob = out + (size_t)bd * TT * HW + w0 + wl2*2;
        for (int p = 0; p < 3; p++) {
            const int h = p * 32 + hs;
            float2 zr[MT], zi[MT];
            UNR<0,MT>([&](auto K){ constexpr int k = decltype(K)::v;
                zr[k] = *reinterpret_cast<const float2*>(Zr + h*ZSTR + k*16 + wl2*2);
                zi[k] = *reinterpret_cast<const float2*>(Zi + h*ZSTR + k*16 + wl2*2); });
            float* op = ob + h * WW;
            {   // t = 0 and t = 16
                float2 s0 = make_float2(0.f, 0.f), s16 = make_float2(0.f, 0.f);
                UNR<0,MT>([&](auto K){ constexpr int k = decltype(K)::v;
                    s0.x += zr[k].x; s0.y += zr[k].y;
                    if constexpr (k & 1) { s16.x -= zr[k].x; s16.y -= zr[k].y; }
                    else                 { s16.x += zr[k].x; s16.y += zr[k].y; } });
                *reinterpret_cast<float2*>(op)                    = s0;
                *reinterpret_cast<float2*>(op + (size_t)16 * HW)  = s16;
            }
            {   // t = 8 and t = 24
                float Cex=0.f, Cey=0.f, Sox=0.f, Soy=0.f;
                UNR<0,4>([&](auto E){ constexpr int k = 2 * decltype(E)::v;
                    Cex = fC<k*8, TT>(zr[k].x, Cex);
                    Cey = fC<k*8, TT>(zr[k].y, Cey); });
                UNR<0,4>([&](auto O){ constexpr int k = 2 * decltype(O)::v + 1;
                    Sox = fS<k*8, TT>(zi[k].x, Sox);
                    Soy = fS<k*8, TT>(zi[k].y, Soy); });
                *reinterpret_cast<float2*>(op + (size_t)8  * HW) = make_float2(Cex - Sox, Cey - Soy);
                *reinterpret_cast<float2*>(op + (size_t)24 * HW) = make_float2(Cex + Sox, Cey + Soy);
            }
            UNR<1,8>([&](auto T){ constexpr int t = decltype(T)::v;
                float Cex=0.f, Cey=0.f, Cox=0.f, Coy=0.f;
                float Sex=0.f, Sey=0.f, Sox=0.f, Soy=0.f;
                UNR<0,4>([&](auto E){ constexpr int k = 2 * decltype(E)::v;
                    Cex = fC<k*t, TT>(zr[k].x, Cex);
                    Cey = fC<k*t, TT>(zr[k].y, Cey);
                    Sex = fS<k*t, TT>(zi[k].x, Sex);
                    Sey = fS<k*t, TT>(zi[k].y, Sey); });
                UNR<0,4>([&](auto O){ constexpr int k = 2 * decltype(O)::v + 1;
                    Cox = fC<k*t, TT>(zr[k].x, Cox);
                    Coy = fC<k*t, TT>(zr[k].y, Coy);
                    Sox = fS<k*t, TT>(zi[k].x, Sox);
                    Soy = fS<k*t, TT>(zi[k].y, Soy); });
                float Cpx = Cex+Cox, Cpy = Cey+Coy, Cmx = Cex-Cox, Cmy = Cey-Coy;
                float Spx = Sex+Sox, Spy = Sey+Soy, Smx = Sex-Sox, Smy = Sey-Soy;
                *reinterpret_cast<float2*>(op + (size_t)t * HW)        = make_float2(Cpx - Spx, Cpy - Spy);
                *reinterpret_cast<float2*>(op + (size_t)(32 - t) * HW) = make_float2(Cpx + Spx, Cpy + Spy);
                *reinterpret_cast<float2*>(op + (size_t)(16 + t) * HW) = make_float2(Cmx - Smx, Cmy - Smy);
                *reinterpret_cast<float2*>(op + (size_t)(16 - t) * HW) = make_float2(Cmx + Smx, Cmy + Smy);
            });
        }
    }
}

// ---------------- launch ----------------
extern "C" void kernel_launch(void* const* d_in, const int* in_sizes, int n_in,
                              void* d_out, int out_size) {
    (void)in_sizes; (void)n_in; (void)out_size;
    const float* x  = (const float*)d_in[0];
    const float* wr = (const float*)d_in[1];
    const float* wi = (const float*)d_in[2];
    float* out = (float*)d_out;

    cudaFuncSetAttribute(kA_fwd, cudaFuncAttributeMaxDynamicSharedMemorySize, SMEM_BYTES);
    cudaFuncSetAttribute(kB_inv, cudaFuncAttributeMaxDynamicSharedMemorySize, SMEM_BYTES);

    kA_fwd <<<1536, 256, SMEM_BYTES>>>(x);    // 256 bc * 6 w-groups
    k3_wdft<<<256,  128>>>();                 // 32768 rows
    k4_mix <<<512,  256>>>(wr, wi);           // 256 mode-groups x 2 c-halves
    kB_inv <<<1536, 256, SMEM_BYTES>>>(out);  // 256 bd * 6 w-groups
}

// round 16
// speedup vs baseline: 1.6319x; 1.0111x over previous
#include <cuda_runtime.h>

// Problem constants
#define BB 8
#define CC 32
#define DD 32
#define TT 32
#define HH 96
#define WW 96
#define MT 8
#define MS 16
#define BC (BB*CC)        // 256
#define BD (BB*DD)        // 256
#define HW (HH*WW)        // 9216
#define NMODE (MT*MS*MS)  // 2048
#define NROW (BC*MT*MS)   // 32768 rows of F2
#define TWO_PI 6.28318530717958647692f

// Y/Z smem row stride (floats). 144: conflict-light in all phases.
#define ZSTR 144
#define SMEM_BYTES (2*HH*ZSTR*4)

// ---------------- scratch (static device globals; no allocation) ----------------
__device__ float g_F2r[WW*NROW];         // after T+H DFT, W-MAJOR: (w, bc*128+kt*16+kx)
__device__ float g_F2i[WW*NROW];
__device__ float g_F3r[BC*NMODE];        // after W-DFT: (bc, m)  m = kt*256+kx*16+ky
__device__ float g_F3i[BC*NMODE];
__device__ float g_Sr [2*BD*NMODE];      // after mix: TWO c-half partials (half, bd, m)
__device__ float g_Si [2*BD*NMODE];

// ---------------- compile-time trig (Taylor, double precision) ----------------
__host__ __device__ constexpr double ct_cos(double x) {
    double x2 = x * x, t = 1.0, s = 1.0;
    for (int k = 1; k <= 26; k++) { t *= -x2 / ((2.0*k - 1.0) * (2.0*k)); s += t; }
    return s;
}
__host__ __device__ constexpr double ct_sin(double x) {
    double x2 = x * x, t = x, s = x;
    for (int k = 1; k <= 26; k++) { t *= -x2 / ((2.0*k) * (2.0*k + 1.0)); s += t; }
    return s;
}

// Twiddle cos/sin(2*pi*P/N) with exact 0 / +-1 at quadrant points
template<int P, int N> struct TW {
    static constexpr int    q0 = ((P % N) + N) % N;
    static constexpr int    aq = (q0 > N - q0) ? (N - q0) : q0;
    static constexpr int    ss = (q0 > N/2) ? -1 : 1;
    static constexpr bool c_zero = (4*aq == N);
    static constexpr bool s_zero = (aq == 0) || (2*aq == N);
    static constexpr float c =
        (aq == 0)     ? 1.0f  :
        (2*aq == N)   ? -1.0f :
        c_zero        ? 0.0f  :
        (float)ct_cos(6.283185307179586476925286766559 * (double)aq / (double)N);
    static constexpr float s =
        s_zero        ? 0.0f :
        (4*aq == N)   ? (ss > 0 ? 1.0f : -1.0f) :
        (float)(ss * ct_sin(6.283185307179586476925286766559 * (double)aq / (double)N));
};

template<int P, int N, int SG = 1>
__device__ __forceinline__ float fC(float v, float acc) {
    using T = TW<P, N>;
    constexpr float cc = (SG < 0) ? -T::c : T::c;
    if constexpr (T::c_zero)         return acc;
    else if constexpr (cc ==  1.0f)  return acc + v;
    else if constexpr (cc == -1.0f)  return acc - v;
    else                             return fmaf(v, cc, acc);
}
template<int P, int N, int SG = 1>
__device__ __forceinline__ float fS(float v, float acc) {
    using T = TW<P, N>;
    constexpr float sv = (SG < 0) ? -T::s : T::s;
    if constexpr (T::s_zero)         return acc;
    else if constexpr (sv ==  1.0f)  return acc + v;
    else if constexpr (sv == -1.0f)  return acc - v;
    else                             return fmaf(v, sv, acc);
}
// float2 lane-wise versions
template<int P, int N, int SG = 1>
__device__ __forceinline__ void fC2(const float2 v, float2& a) {
    a.x = fC<P,N,SG>(v.x, a.x); a.y = fC<P,N,SG>(v.y, a.y);
}
template<int P, int N, int SG = 1>
__device__ __forceinline__ void fS2(const float2 v, float2& a) {
    a.x = fS<P,N,SG>(v.x, a.x); a.y = fS<P,N,SG>(v.y, a.y);
}
__device__ __forceinline__ float4 f4add(const float4 a, const float4 b) {
    return make_float4(a.x+b.x, a.y+b.y, a.z+b.z, a.w+b.w);
}

// ---------------- compile-time unroller ----------------
template<int I> struct Ic { static constexpr int v = I; };
template<int I, int E, class F> __device__ __forceinline__ void UNR(F&& f) {
    if constexpr (I < E) { f(Ic<I>{}); UNR<I+1, E>(f); }
}

// ---------------- KA: fused T-DFT + H-DFT  (x -> F2, w-major) ----------------
__global__ void __maxnreg__(112) kA_fwd(const float* __restrict__ x) {
    extern __shared__ float sm[];
    float* Yr = sm;                     // HH*ZSTR floats
    float* Yi = sm + HH*ZSTR;
    const int tid = threadIdx.x;
    const int bc = blockIdx.x / 6;
    const int w0 = (blockIdx.x % 6) * 16;
    const float* xb = x + (size_t)bc * TT * HW + w0;

    // phase1: T-DFT (real -> complex), float2 lanes (2 w per thread), quad-streamed.
    {
        const int wl2 = tid & 7;
        const int hs  = tid >> 3;           // 0..31
        for (int p = 0; p < 3; p++) {
            const int h = p * 32 + hs;
            const float* xp = xb + h * WW + wl2 * 2;
            float2 ar[MT], ai[MT];
            {   // t = 0/16 and 8/24 specials
                float2 x0  = *reinterpret_cast<const float2*>(xp);
                float2 x8  = *reinterpret_cast<const float2*>(xp + (size_t)8  * HW);
                float2 x16 = *reinterpret_cast<const float2*>(xp + (size_t)16 * HW);
                float2 x24 = *reinterpret_cast<const float2*>(xp + (size_t)24 * HW);
                float2 xe0 = make_float2(x0.x + x16.x, x0.y + x16.y);
                float2 xo0 = make_float2(x0.x - x16.x, x0.y - x16.y);
                float2 xe8 = make_float2(x8.x + x24.x, x8.y + x24.y);
                float2 xo8 = make_float2(x8.x - x24.x, x8.y - x24.y);
                UNR<0,MT>([&](auto K){ constexpr int k = decltype(K)::v;
                    if constexpr ((k & 1) == 0) {
                        float2 t = xe0; fC2<k*8, TT>(xe8, t);
                        ar[k] = t; ai[k] = make_float2(0.f, 0.f);
                    } else {
                        ar[k] = xo0;
                        float2 t = make_float2(0.f, 0.f); fS2<k*8, TT, -1>(xo8, t);
                        ai[k] = t;
                    }
                });
            }
            UNR<1,8>([&](auto T){ constexpr int t = decltype(T)::v;
                float2 a = *reinterpret_cast<const float2*>(xp + (size_t)t        * HW);
                float2 b = *reinterpret_cast<const float2*>(xp + (size_t)(32 - t) * HW);
                float2 c = *reinterpret_cast<const float2*>(xp + (size_t)(16 - t) * HW);
                float2 d = *reinterpret_cast<const float2*>(xp + (size_t)(16 + t) * HW);
                float2 et = make_float2(a.x + d.x, a.y + d.y);   // xe[t]
                float2 ot = make_float2(a.x - d.x, a.y - d.y);   // xo[t]
                float2 em = make_float2(c.x + b.x, c.y + b.y);   // xe[16-t]
                float2 om = make_float2(c.x - b.x, c.y - b.y);   // xo[16-t]
                float2 pe = make_float2(et.x + em.x, et.y + em.y);
                float2 me = make_float2(et.x - em.x, et.y - em.y);
                float2 po = make_float2(ot.x + om.x, ot.y + om.y);
                float2 mo = make_float2(ot.x - om.x, ot.y - om.y);
                UNR<0,MT>([&](auto K){ constexpr int k = decltype(K)::v;
                    if constexpr ((k & 1) == 0) {
                        fC2<k*t, TT>(pe, ar[k]);
                        fS2<k*t, TT, -1>(me, ai[k]);
                    } else {
                        fC2<k*t, TT>(mo, ar[k]);
                        fS2<k*t, TT, -1>(po, ai[k]);
                    }
                });
            });
            UNR<0,MT>([&](auto K){ constexpr int k = decltype(K)::v;
                *reinterpret_cast<float2*>(Yr + h*ZSTR + k*16 + wl2*2) = ar[k];
                *reinterpret_cast<float2*>(Yi + h*ZSTR + k*16 + wl2*2) = ai[k]; });
        }
    }
    __syncthreads();

    // phase2: H-DFT. Even/odd kx banks + 48-domain mirror. kx split in halves.
    {
        const int wl   = tid & 15;
        const int kt   = (tid >> 4) & 7;
        const int half = tid >> 7;
        const float* yr = Yr + kt*16 + wl;
        const float* yi = Yi + kt*16 + wl;
        auto run = [&](auto K0C){
            constexpr int K0 = decltype(K0C)::v;
            float fr[8], fi[8];
            {   // self-paired points: rows {0,48} and {24,72}
                float y0r = yr[0],        y0i = yi[0];
                float y48r = yr[48*ZSTR], y48i = yi[48*ZSTR];
                float y24r = yr[24*ZSTR], y24i = yi[24*ZSTR];
                float y72r = yr[72*ZSTR], y72i = yi[72*ZSTR];
                float u0r = y0r + y48r,  u0i = y0i + y48i;
                float v0r = y0r - y48r,  v0i = y0i - y48i;
                float u24r = y24r + y72r, u24i = y24i + y72i;
                float v24r = y24r - y72r, v24i = y24i - y72i;
                UNR<0,8>([&](auto J){ constexpr int j = decltype(J)::v; constexpr int kx = K0 + j;
                    if constexpr ((kx & 1) == 0) {
                        fr[j] = fC<kx*24, HH>(u24r, u0r);
                        fi[j] = fC<kx*24, HH>(u24i, u0i);
                    } else {
                        fr[j] = fS<kx*24, HH>(v24i, v0r);
                        fi[j] = fS<kx*24, HH, -1>(v24r, v0i);
                    }
                });
            }
            UNR<1,24>([&](auto H){ constexpr int h = decltype(H)::v;
                float yar = yr[h*ZSTR],      yai = yi[h*ZSTR];
                float ybr = yr[(96-h)*ZSTR], ybi = yi[(96-h)*ZSTR];
                float ycr = yr[(48+h)*ZSTR], yci = yi[(48+h)*ZSTR];
                float ydr = yr[(48-h)*ZSTR], ydi = yi[(48-h)*ZSTR];
                float uar = yar + ycr, uai = yai + yci;
                float ubr = ydr + ybr, ubi = ydi + ybi;
                float pa = uar + ubr, ma = uar - ubr;
                float pb = uai + ubi, mb = uai - ubi;
                float var_ = yar - ycr, vai = yai - yci;
                float vbr  = ydr - ybr, vbi = ydi - ybi;
                float qa = var_ - vbr, qm = var_ + vbr;
                float qb = vai - vbi,  qp = vai + vbi;
                UNR<0,8>([&](auto J){ constexpr int j = decltype(J)::v; constexpr int kx = K0 + j;
                    if constexpr ((kx & 1) == 0) {
                        fr[j] = fC<kx*h, HH>(pa, fS<kx*h, HH>(mb, fr[j]));
                        fi[j] = fC<kx*h, HH>(pb, fS<kx*h, HH, -1>(ma, fi[j]));
                    } else {
                        fr[j] = fC<kx*h, HH>(qa, fS<kx*h, HH>(qp, fr[j]));
                        fi[j] = fC<kx*h, HH>(qb, fS<kx*h, HH, -1>(qm, fi[j]));
                    }
                });
            });
            size_t base = (size_t)(w0 + wl) * NROW + bc*128 + kt*16 + K0;
            *reinterpret_cast<float4*>(g_F2r + base)     = make_float4(fr[0], fr[1], fr[2], fr[3]);
            *reinterpret_cast<float4*>(g_F2r + base + 4) = make_float4(fr[4], fr[5], fr[6], fr[7]);
            *reinterpret_cast<float4*>(g_F2i + base)     = make_float4(fi[0], fi[1], fi[2], fi[3]);
            *reinterpret_cast<float4*>(g_F2i + base + 4) = make_float4(fi[4], fi[5], fi[6], fi[7]);
        };
        if (half == 0) run(Ic<0>{}); else run(Ic<8>{});
    }
}

// ---------------- K3: W-DFT (F2 -> F3), coalesced, folded over w <-> 96-w ----------------
__global__ void __launch_bounds__(128) k3_wdft() {
    int r = blockIdx.x * 128 + threadIdx.x;       // 32768 rows, exact
    const float* pr = g_F2r + r;
    const float* pi = g_F2i + r;
    float fr[MS], fi[MS];
    {
        float a0  = pr[0],                  b0  = pi[0];
        float a48 = pr[(size_t)48 * NROW],  b48 = pi[(size_t)48 * NROW];
        UNR<0,MS>([&](auto K){ constexpr int ky = decltype(K)::v;
            fr[ky] = (ky & 1) ? (a0 - a48) : (a0 + a48);
            fi[ky] = (ky & 1) ? (b0 - b48) : (b0 + b48); });
    }
    UNR<1,48>([&](auto WI){ constexpr int w = decltype(WI)::v;
        float a  = pr[(size_t)w * NROW],      b  = pi[(size_t)w * NROW];
        float a2 = pr[(size_t)(96-w) * NROW], b2 = pi[(size_t)(96-w) * NROW];
        float pa = a + a2, ma = a - a2, pb = b + b2, mb = b - b2;
        UNR<0,MS>([&](auto K){ constexpr int ky = decltype(K)::v;
            fr[ky] = fC<w*ky, WW>(pa, fS<w*ky, WW>(mb, fr[ky]));
            fi[ky] = fC<w*ky, WW>(pb, fS<w*ky, WW, -1>(ma, fi[ky]));
        });
    });
    size_t o = (size_t)r * MS;
    UNR<0,MS>([&](auto K){ constexpr int ky = decltype(K)::v;
        g_F3r[o + ky] = fr[ky];
        g_F3i[o + ky] = fi[ky]; });
}

// ---------------- K4: channel mix, c-SPLIT (2 halves), weights ORIGINAL layout ----------------
__global__ void __launch_bounds__(256) k4_mix(const float* __restrict__ wr,
                                              const float* __restrict__ wi) {
    __shared__ float Xr[BB*16*8], Xi[BB*16*8];   // 8 KB (b, c-local, m-local)
    const int m0 = (blockIdx.x >> 1) * 8;
    const int ch = blockIdx.x & 1;
    const int tid = threadIdx.x;
    for (int i = tid; i < BB*16*8; i += 256) {
        int bcl = i >> 3;                 // b*16 + cl
        int b = bcl >> 4, cl = bcl & 15, mm = i & 7;
        size_t src = (size_t)(b*CC + ch*16 + cl) * NMODE + m0 + mm;
        Xr[i] = g_F3r[src];
        Xi[i] = g_F3i[src];
    }
    __syncthreads();
    const int d  = tid >> 3;
    const int ml = tid & 7;
    const int m  = m0 + ml;
    const float* wrp = wr + ((size_t)(ch*16) * DD + d) * NMODE + m;
    const float* wip = wi + ((size_t)(ch*16) * DD + d) * NMODE + m;

    float sr[BB], si[BB];
#pragma unroll
    for (int b = 0; b < BB; b++) { sr[b] = 0.0f; si[b] = 0.0f; }

#pragma unroll
    for (int cl = 0; cl < 16; cl++) {
        float a  = wrp[(size_t)cl * DD * NMODE];
        float bb = wip[(size_t)cl * DD * NMODE];
#pragma unroll
        for (int b = 0; b < BB; b++) {
            float xr = Xr[(b*16 + cl)*8 + ml];
            float xi = Xi[(b*16 + cl)*8 + ml];
            sr[b] = fmaf(xr, a,  fmaf(-xi, bb, sr[b]));
            si[b] = fmaf(xr, bb, fmaf( xi, a,  si[b]));
        }
    }
    float sc = (((m & (MS-1)) == 0) ? 1.0f : 2.0f) * (1.0f / 294912.0f);
#pragma unroll
    for (int b = 0; b < BB; b++) {
        size_t o = (size_t)ch * BD * NMODE + (size_t)(b*DD + d) * NMODE + m;
        g_Sr[o] = sr[b] * sc;
        g_Si[o] = si[b] * sc;
    }
}

// ---------------- KB: fused W-exp + H-exp + T-exp  (S -> out) ----------------
// phase0 DEDUPLICATED: each thread computes only its half's 8 kx (saves 512
// 3-reg FMAs/thread), exchanges via a small aliased smem buffer, prefetches
// the full a1[16] into registers before phase1 overwrites the staging region.
__global__ void __maxnreg__(112) kB_inv(float* __restrict__ out) {
    extern __shared__ float sm[];
    float* Zr  = sm;                             // HH*ZSTR floats
    float* Zi  = sm + HH*ZSTR;
    float*  Ssr = sm;                            // [0..2048)   staging aliases Z
    float*  Ssi = sm + 2048;                     // [2048..4096)
    float2* tab = reinterpret_cast<float2*>(sm + 4096);   // [4096..4608) 256 float2
    float*  A1r = sm + 4608;                     // [4608..6656)  [kx][128]
    float*  A1i = sm + 6656;                     // [6656..8704)  (< HH*ZSTR = 13824)

    const int tid = threadIdx.x;
    const int bd = blockIdx.x / 6;
    const int w0 = (blockIdx.x % 6) * 16;
    const int wl = tid & 15;
    const int kt = (tid >> 4) & 7;
    const int half = tid >> 7;

    {   // load S tile = sum of the two c-half partials (coalesced, float4)
        const float4* s0r = reinterpret_cast<const float4*>(g_Sr + (size_t)bd * NMODE);
        const float4* s1r = reinterpret_cast<const float4*>(g_Sr + (size_t)BD * NMODE + (size_t)bd * NMODE);
        const float4* s0i = reinterpret_cast<const float4*>(g_Si + (size_t)bd * NMODE);
        const float4* s1i = reinterpret_cast<const float4*>(g_Si + (size_t)BD * NMODE + (size_t)bd * NMODE);
#pragma unroll
        for (int q = 0; q < 2; q++) {
            int i = tid + q*256;
            reinterpret_cast<float4*>(Ssr)[i] = f4add(s0r[i], s1r[i]);
            reinterpret_cast<float4*>(Ssi)[i] = f4add(s0i[i], s1i[i]);
        }
        {
            int ky = tid >> 4, wl2 = tid & 15;
            float ssin, ccos;
            sincosf(TWO_PI * (float)((ky * (w0 + wl2)) % WW) / (float)WW, &ssin, &ccos);
            tab[tid] = make_float2(ccos, ssin);
        }
    }
    __syncthreads();

    // phase0: W-expand, e^{+i 2pi ky w / 96}; each half computes 8 kx -> A1 smem.
    {
        float ec[MS], es[MS];
#pragma unroll
        for (int ky = 0; ky < MS; ky++) { float2 e = tab[ky*16 + wl]; ec[ky] = e.x; es[ky] = e.y; }
        const int kx0 = half * 8;
#pragma unroll
        for (int j = 0; j < 8; j++) {
            int kx = kx0 + j;
            const float4* pr4 = reinterpret_cast<const float4*>(Ssr + (kt*MS + kx) * MS);
            const float4* pi4 = reinterpret_cast<const float4*>(Ssi + (kt*MS + kx) * MS);
            float rr = 0.f, ii = 0.f;
#pragma unroll
            for (int q = 0; q < 4; q++) {
                float4 vr = pr4[q];
                float4 vi = pi4[q];
                rr = fmaf(vr.x, ec[q*4+0], fmaf(-vi.x, es[q*4+0], rr));
                ii = fmaf(vr.x, es[q*4+0], fmaf( vi.x, ec[q*4+0], ii));
                rr = fmaf(vr.y, ec[q*4+1], fmaf(-vi.y, es[q*4+1], rr));
                ii = fmaf(vr.y, es[q*4+1], fmaf( vi.y, ec[q*4+1], ii));
                rr = fmaf(vr.z, ec[q*4+2], fmaf(-vi.z, es[q*4+2], rr));
                ii = fmaf(vr.z, es[q*4+2], fmaf( vi.z, ec[q*4+2], ii));
                rr = fmaf(vr.w, ec[q*4+3], fmaf(-vi.w, es[q*4+3], rr));
                ii = fmaf(vr.w, es[q*4+3], fmaf( vi.w, ec[q*4+3], ii));
            }
            A1r[kx*128 + kt*16 + wl] = rr;
            A1i[kx*128 + kt*16 + wl] = ii;
        }
    }
    __syncthreads();

    // prefetch full a1[16] into registers (conflict-free: 32 consecutive per warp)
    float a1r[MS], a1i[MS];
#pragma unroll
    for (int kx = 0; kx < MS; kx++) {
        a1r[kx] = A1r[kx*128 + kt*16 + wl];
        a1i[kx] = A1i[kx*128 + kt*16 + wl];
    }
    __syncthreads();   // all staging/A1 reads done before Z overwrites

    // phase1: H-expand with quad fold {h, 96-h, 48+h, 48-h} via even/odd kx chains.
    {
        auto quad = [&](auto H){ constexpr int h = decltype(H)::v;
            float Ce=0.f, Co=0.f, Se=0.f, So=0.f, C2e=0.f, C2o=0.f, S2e=0.f, S2o=0.f;
            UNR<0,8>([&](auto E){ constexpr int kx = 2 * decltype(E)::v;
                Ce  = fC<kx*h, HH>(a1r[kx], Ce);
                C2e = fC<kx*h, HH>(a1i[kx], C2e);
                Se  = fS<kx*h, HH>(a1i[kx], Se);
                S2e = fS<kx*h, HH>(a1r[kx], S2e);
            });
            UNR<0,8>([&](auto O){ constexpr int kx = 2 * decltype(O)::v + 1;
                Co  = fC<kx*h, HH>(a1r[kx], Co);
                C2o = fC<kx*h, HH>(a1i[kx], C2o);
                So  = fS<kx*h, HH>(a1i[kx], So);
                S2o = fS<kx*h, HH>(a1r[kx], S2o);
            });
            float Cp = Ce+Co, Cm = Ce-Co, Sp = Se+So, Sm = Se-So;
            float C2p = C2e+C2o, C2m = C2e-C2o, S2p = S2e+S2o, S2m = S2e-S2o;
            Zr[h*ZSTR + kt*16 + wl]      = Cp - Sp;
            Zi[h*ZSTR + kt*16 + wl]      = C2p + S2p;
            Zr[(96-h)*ZSTR + kt*16 + wl] = Cp + Sp;
            Zi[(96-h)*ZSTR + kt*16 + wl] = C2p - S2p;
            Zr[(48+h)*ZSTR + kt*16 + wl] = Cm - Sm;
            Zi[(48+h)*ZSTR + kt*16 + wl] = C2m + S2m;
            Zr[(48-h)*ZSTR + kt*16 + wl] = Cm + Sm;
            Zi[(48-h)*ZSTR + kt*16 + wl] = C2m - S2m;
        };
        if (half == 0) {
            {   // self points {0, 48}
                float s0r=0.f, s0i=0.f, s48r=0.f, s48i=0.f;
                UNR<0,MS>([&](auto K){ constexpr int kx = decltype(K)::v;
                    s0r += a1r[kx]; s0i += a1i[kx];
                    if constexpr (kx & 1) { s48r -= a1r[kx]; s48i -= a1i[kx]; }
                    else                  { s48r += a1r[kx]; s48i += a1i[kx]; } });
                Zr[0*ZSTR + kt*16 + wl]  = s0r;  Zi[0*ZSTR + kt*16 + wl]  = s0i;
                Zr[48*ZSTR + kt*16 + wl] = s48r; Zi[48*ZSTR + kt*16 + wl] = s48i;
            }
            UNR<1,13>(quad);
        } else {
            UNR<13,25>(quad);
        }
    }
    __syncthreads();

    // phase2: T-expand + real part, quad fold {t, 32-t, 16+t, 16-t}; float2 lanes.
    {
        const int wl2 = tid & 7;
        const int hs  = tid >> 3;           // 0..31
        float* ob = out + (size_t)bd * TT * HW + w0 + wl2*2;
        for (int p = 0; p < 3; p++) {
            const int h = p * 32 + hs;
            float2 zr[MT], zi[MT];
            UNR<0,MT>([&](auto K){ constexpr int k = decltype(K)::v;
                zr[k] = *reinterpret_cast<const float2*>(Zr + h*ZSTR + k*16 + wl2*2);
                zi[k] = *reinterpret_cast<const float2*>(Zi + h*ZSTR + k*16 + wl2*2); });
            float* op = ob + h * WW;
            {   // t = 0 and t = 16
                float2 s0 = make_float2(0.f, 0.f), s16 = make_float2(0.f, 0.f);
                UNR<0,MT>([&](auto K){ constexpr int k = decltype(K)::v;
                    s0.x += zr[k].x; s0.y += zr[k].y;
                    if constexpr (k & 1) { s16.x -= zr[k].x; s16.y -= zr[k].y; }
                    else                 { s16.x += zr[k].x; s16.y += zr[k].y; } });
                *reinterpret_cast<float2*>(op)                    = s0;
                *reinterpret_cast<float2*>(op + (size_t)16 * HW)  = s16;
            }
            {   // t = 8 and t = 24
                float Cex=0.f, Cey=0.f, Sox=0.f, Soy=0.f;
                UNR<0,4>([&](auto E){ constexpr int k = 2 * decltype(E)::v;
                    Cex = fC<k*8, TT>(zr[k].x, Cex);
                    Cey = fC<k*8, TT>(zr[k].y, Cey); });
                UNR<0,4>([&](auto O){ constexpr int k = 2 * decltype(O)::v + 1;
                    Sox = fS<k*8, TT>(zi[k].x, Sox);
                    Soy = fS<k*8, TT>(zi[k].y, Soy); });
                *reinterpret_cast<float2*>(op + (size_t)8  * HW) = make_float2(Cex - Sox, Cey - Soy);
                *reinterpret_cast<float2*>(op + (size_t)24 * HW) = make_float2(Cex + Sox, Cey + Soy);
            }
            UNR<1,8>([&](auto T){ constexpr int t = decltype(T)::v;
                float Cex=0.f, Cey=0.f, Cox=0.f, Coy=0.f;
                float Sex=0.f, Sey=0.f, Sox=0.f, Soy=0.f;
                UNR<0,4>([&](auto E){ constexpr int k = 2 * decltype(E)::v;
                    Cex = fC<k*t, TT>(zr[k].x, Cex);
                    Cey = fC<k*t, TT>(zr[k].y, Cey);
                    Sex = fS<k*t, TT>(zi[k].x, Sex);
                    Sey = fS<k*t, TT>(zi[k].y, Sey); });
                UNR<0,4>([&](auto O){ constexpr int k = 2 * decltype(O)::v + 1;
                    Cox = fC<k*t, TT>(zr[k].x, Cox);
                    Coy = fC<k*t, TT>(zr[k].y, Coy);
                    Sox = fS<k*t, TT>(zi[k].x, Sox);
                    Soy = fS<k*t, TT>(zi[k].y, Soy); });
                float Cpx = Cex+Cox, Cpy = Cey+Coy, Cmx = Cex-Cox, Cmy = Cey-Coy;
                float Spx = Sex+Sox, Spy = Sey+Soy, Smx = Sex-Sox, Smy = Sey-Soy;
                *reinterpret_cast<float2*>(op + (size_t)t * HW)        = make_float2(Cpx - Spx, Cpy - Spy);
                *reinterpret_cast<float2*>(op + (size_t)(32 - t) * HW) = make_float2(Cpx + Spx, Cpy + Spy);
                *reinterpret_cast<float2*>(op + (size_t)(16 + t) * HW) = make_float2(Cmx - Smx, Cmy - Smy);
                *reinterpret_cast<float2*>(op + (size_t)(16 - t) * HW) = make_float2(Cmx + Smx, Cmy + Smy);
            });
        }
    }
}

// ---------------- launch ----------------
extern "C" void kernel_launch(void* const* d_in, const int* in_sizes, int n_in,
                              void* d_out, int out_size) {
    (void)in_sizes; (void)n_in; (void)out_size;
    const float* x  = (const float*)d_in[0];
    const float* wr = (const float*)d_in[1];
    const float* wi = (const float*)d_in[2];
    float* out = (float*)d_out;

    cudaFuncSetAttribute(kA_fwd, cudaFuncAttributeMaxDynamicSharedMemorySize, SMEM_BYTES);
    cudaFuncSetAttribute(kB_inv, cudaFuncAttributeMaxDynamicSharedMemorySize, SMEM_BYTES);

    kA_fwd <<<1536, 256, SMEM_BYTES>>>(x);    // 256 bc * 6 w-groups
    k3_wdft<<<256,  128>>>();                 // 32768 rows
    k4_mix <<<512,  256>>>(wr, wi);           // 256 mode-groups x 2 c-halves
    kB_inv <<<1536, 256, SMEM_BYTES>>>(out);  // 256 bd * 6 w-groups
}

// round 17
// speedup vs baseline: 1.6536x; 1.0133x over previous
#include <cuda_runtime.h>

// Problem constants
#define BB 8
#define CC 32
#define DD 32
#define TT 32
#define HH 96
#define WW 96
#define MT 8
#define MS 16
#define BC (BB*CC)        // 256
#define BD (BB*DD)        // 256
#define HW (HH*WW)        // 9216
#define NMODE (MT*MS*MS)  // 2048
#define NROW (BC*MT*MS)   // 32768 rows of F2
#define TWO_PI 6.28318530717958647692f

// Y/Z smem row stride (floats). 144: conflict-light in all phases.
#define ZSTR 144
#define SMEM_BYTES (2*HH*ZSTR*4)

// ---------------- scratch (static device globals; no allocation) ----------------
__device__ float g_F2r[WW*NROW];         // after T+H DFT, W-MAJOR: (w, bc*128+kt*16+kx)
__device__ float g_F2i[WW*NROW];
__device__ float g_F3r[BC*NMODE];        // after W-DFT: (bc, m)  m = kt*256+kx*16+ky
__device__ float g_F3i[BC*NMODE];
__device__ float g_Sr [2*BD*NMODE];      // after mix: TWO c-half partials (half, bd, m)
__device__ float g_Si [2*BD*NMODE];

// ---------------- compile-time trig (Taylor, double precision) ----------------
__host__ __device__ constexpr double ct_cos(double x) {
    double x2 = x * x, t = 1.0, s = 1.0;
    for (int k = 1; k <= 26; k++) { t *= -x2 / ((2.0*k - 1.0) * (2.0*k)); s += t; }
    return s;
}
__host__ __device__ constexpr double ct_sin(double x) {
    double x2 = x * x, t = x, s = x;
    for (int k = 1; k <= 26; k++) { t *= -x2 / ((2.0*k) * (2.0*k + 1.0)); s += t; }
    return s;
}

// Twiddle cos/sin(2*pi*P/N) with exact 0 / +-1 at quadrant points
template<int P, int N> struct TW {
    static constexpr int    q0 = ((P % N) + N) % N;
    static constexpr int    aq = (q0 > N - q0) ? (N - q0) : q0;
    static constexpr int    ss = (q0 > N/2) ? -1 : 1;
    static constexpr bool c_zero = (4*aq == N);
    static constexpr bool s_zero = (aq == 0) || (2*aq == N);
    static constexpr float c =
        (aq == 0)     ? 1.0f  :
        (2*aq == N)   ? -1.0f :
        c_zero        ? 0.0f  :
        (float)ct_cos(6.283185307179586476925286766559 * (double)aq / (double)N);
    static constexpr float s =
        s_zero        ? 0.0f :
        (4*aq == N)   ? (ss > 0 ? 1.0f : -1.0f) :
        (float)(ss * ct_sin(6.283185307179586476925286766559 * (double)aq / (double)N));
};

template<int P, int N, int SG = 1>
__device__ __forceinline__ float fC(float v, float acc) {
    using T = TW<P, N>;
    constexpr float cc = (SG < 0) ? -T::c : T::c;
    if constexpr (T::c_zero)         return acc;
    else if constexpr (cc ==  1.0f)  return acc + v;
    else if constexpr (cc == -1.0f)  return acc - v;
    else                             return fmaf(v, cc, acc);
}
template<int P, int N, int SG = 1>
__device__ __forceinline__ float fS(float v, float acc) {
    using T = TW<P, N>;
    constexpr float sv = (SG < 0) ? -T::s : T::s;
    if constexpr (T::s_zero)         return acc;
    else if constexpr (sv ==  1.0f)  return acc + v;
    else if constexpr (sv == -1.0f)  return acc - v;
    else                             return fmaf(v, sv, acc);
}
// float2 lane-wise versions
template<int P, int N, int SG = 1>
__device__ __forceinline__ void fC2(const float2 v, float2& a) {
    a.x = fC<P,N,SG>(v.x, a.x); a.y = fC<P,N,SG>(v.y, a.y);
}
template<int P, int N, int SG = 1>
__device__ __forceinline__ void fS2(const float2 v, float2& a) {
    a.x = fS<P,N,SG>(v.x, a.x); a.y = fS<P,N,SG>(v.y, a.y);
}
__device__ __forceinline__ float4 f4add(const float4 a, const float4 b) {
    return make_float4(a.x+b.x, a.y+b.y, a.z+b.z, a.w+b.w);
}

// ---------------- compile-time unroller ----------------
template<int I> struct Ic { static constexpr int v = I; };
template<int I, int E, class F> __device__ __forceinline__ void UNR(F&& f) {
    if constexpr (I < E) { f(Ic<I>{}); UNR<I+1, E>(f); }
}

// ---------------- KA: fused T-DFT + H-DFT  (x -> F2, w-major) ----------------
__global__ void __maxnreg__(112) kA_fwd(const float* __restrict__ x) {
    extern __shared__ float sm[];
    float* Yr = sm;                     // HH*ZSTR floats
    float* Yi = sm + HH*ZSTR;
    const int tid = threadIdx.x;
    const int bc = blockIdx.x / 6;
    const int w0 = (blockIdx.x % 6) * 16;
    const float* xb = x + (size_t)bc * TT * HW + w0;

    // phase1: T-DFT (real -> complex), float2 lanes (2 w per thread), quad-streamed.
    {
        const int wl2 = tid & 7;
        const int hs  = tid >> 3;           // 0..31
        for (int p = 0; p < 3; p++) {
            const int h = p * 32 + hs;
            const float* xp = xb + h * WW + wl2 * 2;
            float2 ar[MT], ai[MT];
            {   // t = 0/16 and 8/24 specials
                float2 x0  = *reinterpret_cast<const float2*>(xp);
                float2 x8  = *reinterpret_cast<const float2*>(xp + (size_t)8  * HW);
                float2 x16 = *reinterpret_cast<const float2*>(xp + (size_t)16 * HW);
                float2 x24 = *reinterpret_cast<const float2*>(xp + (size_t)24 * HW);
                float2 xe0 = make_float2(x0.x + x16.x, x0.y + x16.y);
                float2 xo0 = make_float2(x0.x - x16.x, x0.y - x16.y);
                float2 xe8 = make_float2(x8.x + x24.x, x8.y + x24.y);
                float2 xo8 = make_float2(x8.x - x24.x, x8.y - x24.y);
                UNR<0,MT>([&](auto K){ constexpr int k = decltype(K)::v;
                    if constexpr ((k & 1) == 0) {
                        float2 t = xe0; fC2<k*8, TT>(xe8, t);
                        ar[k] = t; ai[k] = make_float2(0.f, 0.f);
                    } else {
                        ar[k] = xo0;
                        float2 t = make_float2(0.f, 0.f); fS2<k*8, TT, -1>(xo8, t);
                        ai[k] = t;
                    }
                });
            }
            UNR<1,8>([&](auto T){ constexpr int t = decltype(T)::v;
                float2 a = *reinterpret_cast<const float2*>(xp + (size_t)t        * HW);
                float2 b = *reinterpret_cast<const float2*>(xp + (size_t)(32 - t) * HW);
                float2 c = *reinterpret_cast<const float2*>(xp + (size_t)(16 - t) * HW);
                float2 d = *reinterpret_cast<const float2*>(xp + (size_t)(16 + t) * HW);
                float2 et = make_float2(a.x + d.x, a.y + d.y);   // xe[t]
                float2 ot = make_float2(a.x - d.x, a.y - d.y);   // xo[t]
                float2 em = make_float2(c.x + b.x, c.y + b.y);   // xe[16-t]
                float2 om = make_float2(c.x - b.x, c.y - b.y);   // xo[16-t]
                float2 pe = make_float2(et.x + em.x, et.y + em.y);
                float2 me = make_float2(et.x - em.x, et.y - em.y);
                float2 po = make_float2(ot.x + om.x, ot.y + om.y);
                float2 mo = make_float2(ot.x - om.x, ot.y - om.y);
                UNR<0,MT>([&](auto K){ constexpr int k = decltype(K)::v;
                    if constexpr ((k & 1) == 0) {
                        fC2<k*t, TT>(pe, ar[k]);
                        fS2<k*t, TT, -1>(me, ai[k]);
                    } else {
                        fC2<k*t, TT>(mo, ar[k]);
                        fS2<k*t, TT, -1>(po, ai[k]);
                    }
                });
            });
            UNR<0,MT>([&](auto K){ constexpr int k = decltype(K)::v;
                *reinterpret_cast<float2*>(Yr + h*ZSTR + k*16 + wl2*2) = ar[k];
                *reinterpret_cast<float2*>(Yi + h*ZSTR + k*16 + wl2*2) = ai[k]; });
        }
    }
    __syncthreads();

    // phase2: H-DFT. Even/odd kx banks + 48-domain mirror. kx split in halves.
    {
        const int wl   = tid & 15;
        const int kt   = (tid >> 4) & 7;
        const int half = tid >> 7;
        const float* yr = Yr + kt*16 + wl;
        const float* yi = Yi + kt*16 + wl;
        auto run = [&](auto K0C){
            constexpr int K0 = decltype(K0C)::v;
            float fr[8], fi[8];
            {   // self-paired points: rows {0,48} and {24,72}
                float y0r = yr[0],        y0i = yi[0];
                float y48r = yr[48*ZSTR], y48i = yi[48*ZSTR];
                float y24r = yr[24*ZSTR], y24i = yi[24*ZSTR];
                float y72r = yr[72*ZSTR], y72i = yi[72*ZSTR];
                float u0r = y0r + y48r,  u0i = y0i + y48i;
                float v0r = y0r - y48r,  v0i = y0i - y48i;
                float u24r = y24r + y72r, u24i = y24i + y72i;
                float v24r = y24r - y72r, v24i = y24i - y72i;
                UNR<0,8>([&](auto J){ constexpr int j = decltype(J)::v; constexpr int kx = K0 + j;
                    if constexpr ((kx & 1) == 0) {
                        fr[j] = fC<kx*24, HH>(u24r, u0r);
                        fi[j] = fC<kx*24, HH>(u24i, u0i);
                    } else {
                        fr[j] = fS<kx*24, HH>(v24i, v0r);
                        fi[j] = fS<kx*24, HH, -1>(v24r, v0i);
                    }
                });
            }
            UNR<1,24>([&](auto H){ constexpr int h = decltype(H)::v;
                float yar = yr[h*ZSTR],      yai = yi[h*ZSTR];
                float ybr = yr[(96-h)*ZSTR], ybi = yi[(96-h)*ZSTR];
                float ycr = yr[(48+h)*ZSTR], yci = yi[(48+h)*ZSTR];
                float ydr = yr[(48-h)*ZSTR], ydi = yi[(48-h)*ZSTR];
                float uar = yar + ycr, uai = yai + yci;
                float ubr = ydr + ybr, ubi = ydi + ybi;
                float pa = uar + ubr, ma = uar - ubr;
                float pb = uai + ubi, mb = uai - ubi;
                float var_ = yar - ycr, vai = yai - yci;
                float vbr  = ydr - ybr, vbi = ydi - ybi;
                float qa = var_ - vbr, qm = var_ + vbr;
                float qb = vai - vbi,  qp = vai + vbi;
                UNR<0,8>([&](auto J){ constexpr int j = decltype(J)::v; constexpr int kx = K0 + j;
                    if constexpr ((kx & 1) == 0) {
                        fr[j] = fC<kx*h, HH>(pa, fS<kx*h, HH>(mb, fr[j]));
                        fi[j] = fC<kx*h, HH>(pb, fS<kx*h, HH, -1>(ma, fi[j]));
                    } else {
                        fr[j] = fC<kx*h, HH>(qa, fS<kx*h, HH>(qp, fr[j]));
                        fi[j] = fC<kx*h, HH>(qb, fS<kx*h, HH, -1>(qm, fi[j]));
                    }
                });
            });
            size_t base = (size_t)(w0 + wl) * NROW + bc*128 + kt*16 + K0;
            *reinterpret_cast<float4*>(g_F2r + base)     = make_float4(fr[0], fr[1], fr[2], fr[3]);
            *reinterpret_cast<float4*>(g_F2r + base + 4) = make_float4(fr[4], fr[5], fr[6], fr[7]);
            *reinterpret_cast<float4*>(g_F2i + base)     = make_float4(fi[0], fi[1], fi[2], fi[3]);
            *reinterpret_cast<float4*>(g_F2i + base + 4) = make_float4(fi[4], fi[5], fi[6], fi[7]);
        };
        if (half == 0) run(Ic<0>{}); else run(Ic<8>{});
    }
}

// ---------------- K3: W-DFT (F2 -> F3), 4-way ky split (warp-uniform constexpr) ----------------
// 512 threads = 128 rows x 4 ky-quarters. Warps covering the same rows load identical
// addresses (L1-deduped); warps/SM 7 -> 28 for latency hiding on the 50 MB F2 stream.
__global__ void __launch_bounds__(512) k3_wdft() {
    const int tid = threadIdx.x;
    const int r   = blockIdx.x * 128 + (tid & 127);   // 256 blocks x 128 rows
    const int kq  = tid >> 7;                         // warp-uniform
    const float* pr = g_F2r + r;
    const float* pi = g_F2i + r;

    auto run = [&](auto KQ){
        constexpr int KY0 = decltype(KQ)::v * 4;
        float fr[4], fi[4];
        {
            float a0  = pr[0],                  b0  = pi[0];
            float a48 = pr[(size_t)48 * NROW],  b48 = pi[(size_t)48 * NROW];
            UNR<0,4>([&](auto J){ constexpr int ky = KY0 + decltype(J)::v; constexpr int j = decltype(J)::v;
                fr[j] = (ky & 1) ? (a0 - a48) : (a0 + a48);
                fi[j] = (ky & 1) ? (b0 - b48) : (b0 + b48); });
        }
        UNR<1,48>([&](auto WI){ constexpr int w = decltype(WI)::v;
            float a  = pr[(size_t)w * NROW],      b  = pi[(size_t)w * NROW];
            float a2 = pr[(size_t)(96-w) * NROW], b2 = pi[(size_t)(96-w) * NROW];
            float pa = a + a2, ma = a - a2, pb = b + b2, mb = b - b2;
            UNR<0,4>([&](auto J){ constexpr int ky = KY0 + decltype(J)::v; constexpr int j = decltype(J)::v;
                fr[j] = fC<w*ky, WW>(pa, fS<w*ky, WW>(mb, fr[j]));
                fi[j] = fC<w*ky, WW>(pb, fS<w*ky, WW, -1>(ma, fi[j]));
            });
        });
        size_t o = (size_t)r * MS + KY0;
        *reinterpret_cast<float4*>(g_F3r + o) = make_float4(fr[0], fr[1], fr[2], fr[3]);
        *reinterpret_cast<float4*>(g_F3i + o) = make_float4(fi[0], fi[1], fi[2], fi[3]);
    };
    if      (kq == 0) run(Ic<0>{});
    else if (kq == 1) run(Ic<1>{});
    else if (kq == 2) run(Ic<2>{});
    else              run(Ic<3>{});
}

// ---------------- K4: channel mix, c-SPLIT (2 halves), weights ORIGINAL layout ----------------
__global__ void __launch_bounds__(256) k4_mix(const float* __restrict__ wr,
                                              const float* __restrict__ wi) {
    __shared__ float Xr[BB*16*8], Xi[BB*16*8];   // 8 KB (b, c-local, m-local)
    const int m0 = (blockIdx.x >> 1) * 8;
    const int ch = blockIdx.x & 1;
    const int tid = threadIdx.x;
    for (int i = tid; i < BB*16*8; i += 256) {
        int bcl = i >> 3;                 // b*16 + cl
        int b = bcl >> 4, cl = bcl & 15, mm = i & 7;
        size_t src = (size_t)(b*CC + ch*16 + cl) * NMODE + m0 + mm;
        Xr[i] = g_F3r[src];
        Xi[i] = g_F3i[src];
    }
    __syncthreads();
    const int d  = tid >> 3;
    const int ml = tid & 7;
    const int m  = m0 + ml;
    const float* wrp = wr + ((size_t)(ch*16) * DD + d) * NMODE + m;
    const float* wip = wi + ((size_t)(ch*16) * DD + d) * NMODE + m;

    float sr[BB], si[BB];
#pragma unroll
    for (int b = 0; b < BB; b++) { sr[b] = 0.0f; si[b] = 0.0f; }

#pragma unroll
    for (int cl = 0; cl < 16; cl++) {
        float a  = wrp[(size_t)cl * DD * NMODE];
        float bb = wip[(size_t)cl * DD * NMODE];
#pragma unroll
        for (int b = 0; b < BB; b++) {
            float xr = Xr[(b*16 + cl)*8 + ml];
            float xi = Xi[(b*16 + cl)*8 + ml];
            sr[b] = fmaf(xr, a,  fmaf(-xi, bb, sr[b]));
            si[b] = fmaf(xr, bb, fmaf( xi, a,  si[b]));
        }
    }
    float sc = (((m & (MS-1)) == 0) ? 1.0f : 2.0f) * (1.0f / 294912.0f);
#pragma unroll
    for (int b = 0; b < BB; b++) {
        size_t o = (size_t)ch * BD * NMODE + (size_t)(b*DD + d) * NMODE + m;
        g_Sr[o] = sr[b] * sc;
        g_Si[o] = si[b] * sc;
    }
}

// ---------------- KB: fused W-exp + H-exp + T-exp  (S -> out) ----------------
// phase0 deduplicated via A1 smem exchange; phase1 quad fold; phase2 float2 quad fold.
__global__ void __maxnreg__(112) kB_inv(float* __restrict__ out) {
    extern __shared__ float sm[];
    float* Zr  = sm;                             // HH*ZSTR floats
    float* Zi  = sm + HH*ZSTR;
    float*  Ssr = sm;                            // [0..2048)   staging aliases Z
    float*  Ssi = sm + 2048;                     // [2048..4096)
    float2* tab = reinterpret_cast<float2*>(sm + 4096);   // [4096..4608) 256 float2
    float*  A1r = sm + 4608;                     // [4608..6656)  [kx][128]
    float*  A1i = sm + 6656;                     // [6656..8704)  (< HH*ZSTR = 13824)

    const int tid = threadIdx.x;
    const int bd = blockIdx.x / 6;
    const int w0 = (blockIdx.x % 6) * 16;
    const int wl = tid & 15;
    const int kt = (tid >> 4) & 7;
    const int half = tid >> 7;

    {   // load S tile = sum of the two c-half partials (coalesced, float4)
        const float4* s0r = reinterpret_cast<const float4*>(g_Sr + (size_t)bd * NMODE);
        const float4* s1r = reinterpret_cast<const float4*>(g_Sr + (size_t)BD * NMODE + (size_t)bd * NMODE);
        const float4* s0i = reinterpret_cast<const float4*>(g_Si + (size_t)bd * NMODE);
        const float4* s1i = reinterpret_cast<const float4*>(g_Si + (size_t)BD * NMODE + (size_t)bd * NMODE);
#pragma unroll
        for (int q = 0; q < 2; q++) {
            int i = tid + q*256;
            reinterpret_cast<float4*>(Ssr)[i] = f4add(s0r[i], s1r[i]);
            reinterpret_cast<float4*>(Ssi)[i] = f4add(s0i[i], s1i[i]);
        }
        {
            int ky = tid >> 4, wl2 = tid & 15;
            float ssin, ccos;
            sincosf(TWO_PI * (float)((ky * (w0 + wl2)) % WW) / (float)WW, &ssin, &ccos);
            tab[tid] = make_float2(ccos, ssin);
        }
    }
    __syncthreads();

    // phase0: W-expand, e^{+i 2pi ky w / 96}; each half computes 8 kx -> A1 smem.
    {
        float ec[MS], es[MS];
#pragma unroll
        for (int ky = 0; ky < MS; ky++) { float2 e = tab[ky*16 + wl]; ec[ky] = e.x; es[ky] = e.y; }
        const int kx0 = half * 8;
#pragma unroll
        for (int j = 0; j < 8; j++) {
            int kx = kx0 + j;
            const float4* pr4 = reinterpret_cast<const float4*>(Ssr + (kt*MS + kx) * MS);
            const float4* pi4 = reinterpret_cast<const float4*>(Ssi + (kt*MS + kx) * MS);
            float rr = 0.f, ii = 0.f;
#pragma unroll
            for (int q = 0; q < 4; q++) {
                float4 vr = pr4[q];
                float4 vi = pi4[q];
                rr = fmaf(vr.x, ec[q*4+0], fmaf(-vi.x, es[q*4+0], rr));
                ii = fmaf(vr.x, es[q*4+0], fmaf( vi.x, ec[q*4+0], ii));
                rr = fmaf(vr.y, ec[q*4+1], fmaf(-vi.y, es[q*4+1], rr));
                ii = fmaf(vr.y, es[q*4+1], fmaf( vi.y, ec[q*4+1], ii));
                rr = fmaf(vr.z, ec[q*4+2], fmaf(-vi.z, es[q*4+2], rr));
                ii = fmaf(vr.z, es[q*4+2], fmaf( vi.z, ec[q*4+2], ii));
                rr = fmaf(vr.w, ec[q*4+3], fmaf(-vi.w, es[q*4+3], rr));
                ii = fmaf(vr.w, es[q*4+3], fmaf( vi.w, ec[q*4+3], ii));
            }
            A1r[kx*128 + kt*16 + wl] = rr;
            A1i[kx*128 + kt*16 + wl] = ii;
        }
    }
    __syncthreads();

    // prefetch full a1[16] into registers (conflict-free: 32 consecutive per warp)
    float a1r[MS], a1i[MS];
#pragma unroll
    for (int kx = 0; kx < MS; kx++) {
        a1r[kx] = A1r[kx*128 + kt*16 + wl];
        a1i[kx] = A1i[kx*128 + kt*16 + wl];
    }
    __syncthreads();   // all staging/A1 reads done before Z overwrites

    // phase1: H-expand with quad fold {h, 96-h, 48+h, 48-h} via even/odd kx chains.
    {
        auto quad = [&](auto H){ constexpr int h = decltype(H)::v;
            float Ce=0.f, Co=0.f, Se=0.f, So=0.f, C2e=0.f, C2o=0.f, S2e=0.f, S2o=0.f;
            UNR<0,8>([&](auto E){ constexpr int kx = 2 * decltype(E)::v;
                Ce  = fC<kx*h, HH>(a1r[kx], Ce);
                C2e = fC<kx*h, HH>(a1i[kx], C2e);
                Se  = fS<kx*h, HH>(a1i[kx], Se);
                S2e = fS<kx*h, HH>(a1r[kx], S2e);
            });
            UNR<0,8>([&](auto O){ constexpr int kx = 2 * decltype(O)::v + 1;
                Co  = fC<kx*h, HH>(a1r[kx], Co);
                C2o = fC<kx*h, HH>(a1i[kx], C2o);
                So  = fS<kx*h, HH>(a1i[kx], So);
                S2o = fS<kx*h, HH>(a1r[kx], S2o);
            });
            float Cp = Ce+Co, Cm = Ce-Co, Sp = Se+So, Sm = Se-So;
            float C2p = C2e+C2o, C2m = C2e-C2o, S2p = S2e+S2o, S2m = S2e-S2o;
            Zr[h*ZSTR + kt*16 + wl]      = Cp - Sp;
            Zi[h*ZSTR + kt*16 + wl]      = C2p + S2p;
            Zr[(96-h)*ZSTR + kt*16 + wl] = Cp + Sp;
            Zi[(96-h)*ZSTR + kt*16 + wl] = C2p - S2p;
            Zr[(48+h)*ZSTR + kt*16 + wl] = Cm - Sm;
            Zi[(48+h)*ZSTR + kt*16 + wl] = C2m + S2m;
            Zr[(48-h)*ZSTR + kt*16 + wl] = Cm + Sm;
            Zi[(48-h)*ZSTR + kt*16 + wl] = C2m - S2m;
        };
        if (half == 0) {
            {   // self points {0, 48}
                float s0r=0.f, s0i=0.f, s48r=0.f, s48i=0.f;
                UNR<0,MS>([&](auto K){ constexpr int kx = decltype(K)::v;
                    s0r += a1r[kx]; s0i += a1i[kx];
                    if constexpr (kx & 1) { s48r -= a1r[kx]; s48i -= a1i[kx]; }
                    else                  { s48r += a1r[kx]; s48i += a1i[kx]; } });
                Zr[0*ZSTR + kt*16 + wl]  = s0r;  Zi[0*ZSTR + kt*16 + wl]  = s0i;
                Zr[48*ZSTR + kt*16 + wl] = s48r; Zi[48*ZSTR + kt*16 + wl] = s48i;
            }
            UNR<1,13>(quad);
        } else {
            UNR<13,25>(quad);
        }
    }
    __syncthreads();

    // phase2: T-expand + real part, quad fold {t, 32-t, 16+t, 16-t}; float2 lanes.
    {
        const int wl2 = tid & 7;
        const int hs  = tid >> 3;           // 0..31
        float* ob = out + (size_t)bd * TT * HW + w0 + wl2*2;
        for (int p = 0; p < 3; p++) {
            const int h = p * 32 + hs;
            float2 zr[MT], zi[MT];
            UNR<0,MT>([&](auto K){ constexpr int k = decltype(K)::v;
                zr[k] = *reinterpret_cast<const float2*>(Zr + h*ZSTR + k*16 + wl2*2);
                zi[k] = *reinterpret_cast<const float2*>(Zi + h*ZSTR + k*16 + wl2*2); });
            float* op = ob + h * WW;
            {   // t = 0 and t = 16
                float2 s0 = make_float2(0.f, 0.f), s16 = make_float2(0.f, 0.f);
                UNR<0,MT>([&](auto K){ constexpr int k = decltype(K)::v;
                    s0.x += zr[k].x; s0.y += zr[k].y;
                    if constexpr (k & 1) { s16.x -= zr[k].x; s16.y -= zr[k].y; }
                    else                 { s16.x += zr[k].x; s16.y += zr[k].y; } });
                *reinterpret_cast<float2*>(op)                    = s0;
                *reinterpret_cast<float2*>(op + (size_t)16 * HW)  = s16;
            }
            {   // t = 8 and t = 24
                float Cex=0.f, Cey=0.f, Sox=0.f, Soy=0.f;
                UNR<0,4>([&](auto E){ constexpr int k = 2 * decltype(E)::v;
                    Cex = fC<k*8, TT>(zr[k].x, Cex);
                    Cey = fC<k*8, TT>(zr[k].y, Cey); });
                UNR<0,4>([&](auto O){ constexpr int k = 2 * decltype(O)::v + 1;
                    Sox = fS<k*8, TT>(zi[k].x, Sox);
                    Soy = fS<k*8, TT>(zi[k].y, Soy); });
                *reinterpret_cast<float2*>(op + (size_t)8  * HW) = make_float2(Cex - Sox, Cey - Soy);
                *reinterpret_cast<float2*>(op + (size_t)24 * HW) = make_float2(Cex + Sox, Cey + Soy);
            }
            UNR<1,8>([&](auto T){ constexpr int t = decltype(T)::v;
                float Cex=0.f, Cey=0.f, Cox=0.f, Coy=0.f;
                float Sex=0.f, Sey=0.f, Sox=0.f, Soy=0.f;
                UNR<0,4>([&](auto E){ constexpr int k = 2 * decltype(E)::v;
                    Cex = fC<k*t, TT>(zr[k].x, Cex);
                    Cey = fC<k*t, TT>(zr[k].y, Cey);
                    Sex = fS<k*t, TT>(zi[k].x, Sex);
                    Sey = fS<k*t, TT>(zi[k].y, Sey); });
                UNR<0,4>([&](auto O){ constexpr int k = 2 * decltype(O)::v + 1;
                    Cox = fC<k*t, TT>(zr[k].x, Cox);
                    Coy = fC<k*t, TT>(zr[k].y, Coy);
                    Sox = fS<k*t, TT>(zi[k].x, Sox);
                    Soy = fS<k*t, TT>(zi[k].y, Soy); });
                float Cpx = Cex+Cox, Cpy = Cey+Coy, Cmx = Cex-Cox, Cmy = Cey-Coy;
                float Spx = Sex+Sox, Spy = Sey+Soy, Smx = Sex-Sox, Smy = Sey-Soy;
                *reinterpret_cast<float2*>(op + (size_t)t * HW)        = make_float2(Cpx - Spx, Cpy - Spy);
                *reinterpret_cast<float2*>(op + (size_t)(32 - t) * HW) = make_float2(Cpx + Spx, Cpy + Spy);
                *reinterpret_cast<float2*>(op + (size_t)(16 + t) * HW) = make_float2(Cmx - Smx, Cmy - Smy);
                *reinterpret_cast<float2*>(op + (size_t)(16 - t) * HW) = make_float2(Cmx + Smx, Cmy + Smy);
            });
        }
    }
}

// ---------------- launch ----------------
extern "C" void kernel_launch(void* const* d_in, const int* in_sizes, int n_in,
                              void* d_out, int out_size) {
    (void)in_sizes; (void)n_in; (void)out_size;
    const float* x  = (const float*)d_in[0];
    const float* wr = (const float*)d_in[1];
    const float* wi = (const float*)d_in[2];
    float* out = (float*)d_out;

    cudaFuncSetAttribute(kA_fwd, cudaFuncAttributeMaxDynamicSharedMemorySize, SMEM_BYTES);
    cudaFuncSetAttribute(kB_inv, cudaFuncAttributeMaxDynamicSharedMemorySize, SMEM_BYTES);

    kA_fwd <<<1536, 256, SMEM_BYTES>>>(x);    // 256 bc * 6 w-groups
    k3_wdft<<<256,  512>>>();                 // 256 blocks x (128 rows x 4 ky-quarters)
    k4_mix <<<512,  256>>>(wr, wi);           // 256 mode-groups x 2 c-halves
    kB_inv <<<1536, 256, SMEM_BYTES>>>(out);  // 256 bd * 6 w-groups
}